// round 1
// baseline (speedup 1.0000x reference)
#include <cuda_runtime.h>
#include <math.h>

#define TOK    4096   // B*N tokens
#define DMODEL 768
#define NSEQ   512
#define NHEAD  8
#define DHEAD  96
#define NFEAT  256
#define NBH    64     // B*H
#define NFF    3072
#define NDEPTH 6

// ---------------- scratch (device globals; no allocations) ----------------
__device__ float g_x[TOK*DMODEL];          // running residual stream
__device__ float g_lnbuf[TOK*DMODEL];      // LN output
__device__ float g_qkv[TOK*3*DMODEL];      // qkv projection
__device__ float g_ffbuf[TOK*NFF];         // ff hidden
__device__ float g_uq[NBH*NSEQ*NFEAT];     // u_q, then pq in place
__device__ float g_uk[NBH*NSEQ*NFEAT];     // u_k, then pk in place
__device__ float g_ctxb[NBH*NFEAT*DHEAD];  // pk^T @ v
__device__ float g_attn[TOK*DMODEL];       // attention output (pre ao_w)
__device__ float g_diag[2*NBH*NSEQ];       // [0]=q diag, [1]=k diag
__device__ float g_pksum[NBH*NFEAT];
__device__ float g_den[NBH*NSEQ];
__device__ float g_im2col[TOK*256];
__device__ float g_pwT[256*DMODEL];
__device__ unsigned g_kmax;                // ordered-uint encoded global max of u_k

// ---------------- helpers ----------------
__device__ __forceinline__ unsigned enc_f(float f){
    unsigned u = __float_as_uint(f);
    return (u & 0x80000000u) ? ~u : (u | 0x80000000u);
}
__device__ __forceinline__ float dec_f(unsigned e){
    return (e & 0x80000000u) ? __uint_as_float(e ^ 0x80000000u) : __uint_as_float(~e);
}
__device__ __forceinline__ float wsum(float v){
    #pragma unroll
    for (int o = 16; o > 0; o >>= 1) v += __shfl_xor_sync(0xffffffffu, v, o);
    return v;
}
__device__ __forceinline__ float wmax(float v){
    #pragma unroll
    for (int o = 16; o > 0; o >>= 1) v = fmaxf(v, __shfl_xor_sync(0xffffffffu, v, o));
    return v;
}

// ---------------- patch embed prep ----------------
__global__ void im2col_kernel(const float* __restrict__ mel, float* __restrict__ dst){
    int idx = blockIdx.x*256 + threadIdx.x;        // 4096*256 total
    int pg = idx >> 8, k = idx & 255;
    int b = pg >> 9, p = pg & 511;
    int oh = p >> 3, ow = p & 7;
    int i = k >> 4, j = k & 15;
    dst[idx] = mel[(size_t)b*131072 + (size_t)(oh*16 + i)*128 + ow*16 + j];
}

__global__ void transpose_pw(const float* __restrict__ pw, float* __restrict__ pwT){
    int idx = blockIdx.x*256 + threadIdx.x;        // 768*256 total
    int d = idx >> 8, k = idx & 255;
    pwT[k*DMODEL + d] = pw[idx];
}

// ---------------- big GEMM: C[M,N] = A[M,K] @ W[K,N] (+ epilogue) ----------------
// ep: 0 = store acc+bias ; 1 = gelu(acc+bias) ; 2 = C += acc+bias (residual)
//     3 = store acc+bias+aux[(row%512)*768+col]  (pos embed add)
__global__ __launch_bounds__(256) void gemm128(
    const float* __restrict__ A, const float* __restrict__ W,
    const float* __restrict__ bias, float* __restrict__ C,
    int K, int Ncols, int ep, const float* __restrict__ aux)
{
    __shared__ __align__(16) float As[16][132];
    __shared__ __align__(16) float Bs[16][128];
    int tid = threadIdx.x;
    int tx = tid & 15, ty = tid >> 4;
    int n0 = blockIdx.x * 128, m0 = blockIdx.y * 128;

    float acc[8][8];
    #pragma unroll
    for (int i = 0; i < 8; i++)
        #pragma unroll
        for (int j = 0; j < 8; j++) acc[i][j] = 0.f;

    for (int k0 = 0; k0 < K; k0 += 16){
        #pragma unroll
        for (int i = 0; i < 2; i++){
            int s = tid + i*256;           // 512 float4 slots for A tile (128x16)
            int r = s >> 2, c4 = s & 3;
            float4 v = *(const float4*)(A + (size_t)(m0 + r)*K + k0 + c4*4);
            As[c4*4+0][r] = v.x; As[c4*4+1][r] = v.y;
            As[c4*4+2][r] = v.z; As[c4*4+3][r] = v.w;
        }
        #pragma unroll
        for (int i = 0; i < 2; i++){
            int s = tid + i*256;           // 512 float4 slots for B tile (16x128)
            int r = s >> 5, c4 = s & 31;
            *(float4*)&Bs[r][c4*4] = *(const float4*)(W + (size_t)(k0 + r)*Ncols + n0 + c4*4);
        }
        __syncthreads();
        #pragma unroll
        for (int kk = 0; kk < 16; kk++){
            float a[8], bv[8];
            *(float4*)(&a[0]) = *(const float4*)(&As[kk][ty*8]);
            *(float4*)(&a[4]) = *(const float4*)(&As[kk][ty*8+4]);
            *(float4*)(&bv[0]) = *(const float4*)(&Bs[kk][tx*8]);
            *(float4*)(&bv[4]) = *(const float4*)(&Bs[kk][tx*8+4]);
            #pragma unroll
            for (int i = 0; i < 8; i++)
                #pragma unroll
                for (int j = 0; j < 8; j++)
                    acc[i][j] = fmaf(a[i], bv[j], acc[i][j]);
        }
        __syncthreads();
    }

    #pragma unroll
    for (int i = 0; i < 8; i++){
        int row = m0 + ty*8 + i;
        float* crow = C + (size_t)row*Ncols;
        const float* arow = aux ? (aux + (size_t)(row & 511)*DMODEL) : (const float*)0;
        #pragma unroll
        for (int j = 0; j < 8; j++){
            int col = n0 + tx*8 + j;
            float v = acc[i][j] + bias[col];
            if (ep == 1)      v = 0.5f*v*(1.0f + erff(v*0.70710678118654752f));
            else if (ep == 2) v += crow[col];
            else if (ep == 3) v += arow[col];
            crow[col] = v;
        }
    }
}

// ---------------- layernorm ----------------
__global__ void ln_kernel(const float* __restrict__ X, const float* __restrict__ sc,
                          const float* __restrict__ bb, float* __restrict__ Y)
{
    __shared__ float s1[8], s2[8];
    int row = blockIdx.x, tid = threadIdx.x;
    int lane = tid & 31, wid = tid >> 5;
    const float* xr = X + (size_t)row*DMODEL;
    float v[3]; float sum = 0.f, sq = 0.f;
    #pragma unroll
    for (int i = 0; i < 3; i++){
        v[i] = xr[tid + 256*i];
        sum += v[i]; sq += v[i]*v[i];
    }
    sum = wsum(sum); sq = wsum(sq);
    if (lane == 0){ s1[wid] = sum; s2[wid] = sq; }
    __syncthreads();
    if (tid == 0){
        float a = 0.f, b2 = 0.f;
        #pragma unroll
        for (int i = 0; i < 8; i++){ a += s1[i]; b2 += s2[i]; }
        s1[0] = a; s2[0] = b2;
    }
    __syncthreads();
    float mean = s1[0]*(1.f/768.f);
    float var  = s2[0]*(1.f/768.f) - mean*mean;
    float rstd = rsqrtf(var + 1e-5f);
    float* yr = Y + (size_t)row*DMODEL;
    #pragma unroll
    for (int i = 0; i < 3; i++){
        int d = tid + 256*i;
        yr[d] = (v[i] - mean)*rstd*sc[d] + bb[d];
    }
}

// ---------------- diag (0.5*||x*d^-1/4||^2) for q and k; resets g_kmax ----------------
__global__ void diag_kernel(const float* __restrict__ qkv, float* __restrict__ diag)
{
    if (blockIdx.x == 0 && threadIdx.x == 0) g_kmax = 0u;
    int gw = blockIdx.x*8 + (threadIdx.x >> 5);  // 0..65535
    int lane = threadIdx.x & 31;
    int which = gw >> 15;          // 0=q, 1=k
    int r = gw & 32767;            // bh*512 + n
    int bh = r >> 9, n = r & 511;
    int b = bh >> 3, h = bh & 7;
    const float* p = qkv + (size_t)(b*512 + n)*2304 + which*768 + h*96;
    float s = 0.f;
    #pragma unroll
    for (int i = 0; i < 3; i++){ float t = p[lane + 32*i]; s += t*t; }
    s = wsum(s);
    if (lane == 0) diag[gw] = 0.05103103631f * s;   // 0.5 / sqrt(96)
}

// ---------------- u = (x * 96^-1/4) @ proj^T  (per b,h) ----------------
__global__ __launch_bounds__(256) void phi_u_kernel(
    const float* __restrict__ qkv, const float* __restrict__ proj,
    float* __restrict__ U, int off, int isk)
{
    __shared__ __align__(16) float Qs[16][68];   // [k][n]
    __shared__ __align__(16) float Ps[16][68];   // [k][m]
    __shared__ float red[256];
    int bh = blockIdx.z, b = bh >> 3, h = bh & 7;
    int n0 = blockIdx.y*64, m0 = blockIdx.x*64;
    int tid = threadIdx.x, tx = tid & 15, ty = tid >> 4;
    const float* Abase = qkv + (size_t)(b*512)*2304 + off + h*96;

    float acc[4][4];
    #pragma unroll
    for (int i = 0; i < 4; i++)
        #pragma unroll
        for (int j = 0; j < 4; j++) acc[i][j] = 0.f;

    for (int k0 = 0; k0 < 96; k0 += 16){
        {
            int r = tid >> 2, c4 = tid & 3;
            float4 v = *(const float4*)(Abase + (size_t)(n0 + r)*2304 + k0 + c4*4);
            Qs[c4*4+0][r] = v.x; Qs[c4*4+1][r] = v.y;
            Qs[c4*4+2][r] = v.z; Qs[c4*4+3][r] = v.w;
        }
        {
            int r = tid >> 2, c4 = tid & 3;
            float4 v = *(const float4*)(proj + (size_t)(m0 + r)*96 + k0 + c4*4);
            Ps[c4*4+0][r] = v.x; Ps[c4*4+1][r] = v.y;
            Ps[c4*4+2][r] = v.z; Ps[c4*4+3][r] = v.w;
        }
        __syncthreads();
        #pragma unroll
        for (int kk = 0; kk < 16; kk++){
            float a[4], bv[4];
            *(float4*)a  = *(const float4*)(&Qs[kk][ty*4]);
            *(float4*)bv = *(const float4*)(&Ps[kk][tx*4]);
            #pragma unroll
            for (int i = 0; i < 4; i++)
                #pragma unroll
                for (int j = 0; j < 4; j++)
                    acc[i][j] = fmaf(a[i], bv[j], acc[i][j]);
        }
        __syncthreads();
    }

    const float cs = 0.31947155f;   // 96^{-1/4}
    float tmax = -1e30f;
    float* Ub = U + ((size_t)bh*512 + n0)*256 + m0;
    #pragma unroll
    for (int i = 0; i < 4; i++)
        #pragma unroll
        for (int j = 0; j < 4; j++){
            float u = acc[i][j]*cs;
            Ub[(size_t)(ty*4 + i)*256 + tx*4 + j] = u;
            tmax = fmaxf(tmax, u);
        }
    if (isk){
        red[tid] = tmax;
        __syncthreads();
        for (int s = 128; s > 0; s >>= 1){
            if (tid < s) red[tid] = fmaxf(red[tid], red[tid + s]);
            __syncthreads();
        }
        if (tid == 0) atomicMax(&g_kmax, enc_f(red[0]));
    }
}

// ---------------- phi finalize ----------------
__global__ void pq_fin(float* __restrict__ U, const float* __restrict__ diagq)
{
    int gw = blockIdx.x*8 + (threadIdx.x >> 5);  // row in [0,32768)
    int lane = threadIdx.x & 31;
    float* u = U + (size_t)gw*256;
    float v[8]; float m = -1e30f;
    #pragma unroll
    for (int i = 0; i < 8; i++){ v[i] = u[lane + 32*i]; m = fmaxf(m, v[i]); }
    m = wmax(m);
    float d = diagq[gw];
    #pragma unroll
    for (int i = 0; i < 8; i++)
        u[lane + 32*i] = (expf(v[i] - d - m) + 1e-4f)*0.0625f;
}

__global__ void pk_fin(float* __restrict__ U, const float* __restrict__ diagk)
{
    float kst = dec_f(g_kmax);
    int i = blockIdx.x*256 + threadIdx.x;   // 8388608 total
    float v = U[i];
    int r = i >> 8;
    U[i] = (expf(v - diagk[r] - kst) + 1e-4f)*0.0625f;
}

__global__ void pksum_kernel(const float* __restrict__ pk, float* __restrict__ ps)
{
    int bh = blockIdx.x, m = threadIdx.x;
    const float* p = pk + (size_t)bh*512*256 + m;
    float s = 0.f;
    for (int n = 0; n < 512; n++) s += p[(size_t)n*256];
    ps[bh*256 + m] = s;
}

__global__ void den_kernel(const float* __restrict__ pq, const float* __restrict__ ps,
                           float* __restrict__ den)
{
    int gw = blockIdx.x*8 + (threadIdx.x >> 5);
    int lane = threadIdx.x & 31;
    int bh = gw >> 9;
    const float* q = pq + (size_t)gw*256;
    const float* s = ps + bh*256;
    float a = 0.f;
    #pragma unroll
    for (int i = 0; i < 8; i++){ int j = lane + 32*i; a += q[j]*s[j]; }
    a = wsum(a);
    if (lane == 0) den[gw] = a;
}

// ---------------- ctx = pk^T @ v  (per b,h): (256m x 96e), K = 512n ----------------
__global__ __launch_bounds__(256) void ctx_kernel(
    const float* __restrict__ pk, const float* __restrict__ qkv, float* __restrict__ ctx)
{
    __shared__ __align__(16) float Ks[16][64];   // [n][m]
    __shared__ float Vs[16][96];                 // [n][e]
    int bh = blockIdx.y, b = bh >> 3, h = bh & 7;
    int m0 = blockIdx.x*64;
    int tid = threadIdx.x, tx = tid & 15, ty = tid >> 4;
    const float* vbase = qkv + (size_t)(b*512)*2304 + 1536 + h*96;

    float acc[4][6];
    #pragma unroll
    for (int i = 0; i < 4; i++)
        #pragma unroll
        for (int j = 0; j < 6; j++) acc[i][j] = 0.f;

    for (int n0 = 0; n0 < 512; n0 += 16){
        {
            int r = tid >> 4, c4 = tid & 15;
            *(float4*)&Ks[r][c4*4] =
                *(const float4*)(pk + ((size_t)bh*512 + n0 + r)*256 + m0 + c4*4);
        }
        #pragma unroll
        for (int i = 0; i < 6; i++){
            int s = tid + i*256;        // 1536 elements
            int r = s/96, c = s - r*96;
            Vs[r][c] = vbase[(size_t)(n0 + r)*2304 + c];
        }
        __syncthreads();
        #pragma unroll
        for (int kk = 0; kk < 16; kk++){
            float a[4];
            *(float4*)a = *(const float4*)(&Ks[kk][ty*4]);
            float bv[6];
            #pragma unroll
            for (int j = 0; j < 6; j++) bv[j] = Vs[kk][tx*6 + j];
            #pragma unroll
            for (int i = 0; i < 4; i++)
                #pragma unroll
                for (int j = 0; j < 6; j++)
                    acc[i][j] = fmaf(a[i], bv[j], acc[i][j]);
        }
        __syncthreads();
    }
    #pragma unroll
    for (int i = 0; i < 4; i++)
        #pragma unroll
        for (int j = 0; j < 6; j++)
            ctx[(size_t)bh*24576 + (size_t)(m0 + ty*4 + i)*96 + tx*6 + j] = acc[i][j];
}

// ---------------- out = (pq @ ctx) / den -> attn[(b,n), h*96+e] ----------------
__global__ __launch_bounds__(256) void attn_out_kernel(
    const float* __restrict__ pq, const float* __restrict__ ctx,
    const float* __restrict__ den, float* __restrict__ attn)
{
    __shared__ __align__(16) float Qs[16][64];   // [m][n]
    __shared__ float Cs[16][96];                 // [m][e]
    int bh = blockIdx.y, b = bh >> 3, h = bh & 7;
    int n0 = blockIdx.x*64;
    int tid = threadIdx.x, tx = tid & 15, ty = tid >> 4;

    float acc[4][6];
    #pragma unroll
    for (int i = 0; i < 4; i++)
        #pragma unroll
        for (int j = 0; j < 6; j++) acc[i][j] = 0.f;

    for (int k0 = 0; k0 < 256; k0 += 16){
        {
            int r = tid >> 2, c4 = tid & 3;
            float4 v = *(const float4*)(pq + ((size_t)bh*512 + n0 + r)*256 + k0 + c4*4);
            Qs[c4*4+0][r] = v.x; Qs[c4*4+1][r] = v.y;
            Qs[c4*4+2][r] = v.z; Qs[c4*4+3][r] = v.w;
        }
        #pragma unroll
        for (int i = 0; i < 6; i++){
            int s = tid + i*256;
            int r = s/96, c = s - r*96;
            Cs[r][c] = ctx[(size_t)bh*24576 + (size_t)(k0 + r)*96 + c];
        }
        __syncthreads();
        #pragma unroll
        for (int kk = 0; kk < 16; kk++){
            float a[4];
            *(float4*)a = *(const float4*)(&Qs[kk][ty*4]);
            float bv[6];
            #pragma unroll
            for (int j = 0; j < 6; j++) bv[j] = Cs[kk][tx*6 + j];
            #pragma unroll
            for (int i = 0; i < 4; i++)
                #pragma unroll
                for (int j = 0; j < 6; j++)
                    acc[i][j] = fmaf(a[i], bv[j], acc[i][j]);
        }
        __syncthreads();
    }
    #pragma unroll
    for (int i = 0; i < 4; i++){
        int n = n0 + ty*4 + i;
        float dinv = 1.f/den[bh*512 + n];
        #pragma unroll
        for (int j = 0; j < 6; j++)
            attn[(size_t)(b*512 + n)*768 + h*96 + tx*6 + j] = acc[i][j]*dinv;
    }
}

// ---------------- mask head: sigmoid(x @ mask_w + mask_b) -> (B, NM, N) ----------------
__global__ void mask_kernel(const float* __restrict__ X, const float* __restrict__ mw,
                            const float* __restrict__ mb, float* __restrict__ out)
{
    int row = blockIdx.x;                 // b*512 + n
    int tid = threadIdx.x;
    int w = tid >> 5, lane = tid & 31;    // 4 warps, one per mask
    const float* xr = X + (size_t)row*768;
    float s = 0.f;
    for (int d = lane; d < 768; d += 32) s += xr[d]*mw[d*4 + w];
    s = wsum(s);
    if (lane == 0){
        float logit = s + mb[w];
        int b = row >> 9, n = row & 511;
        out[((size_t)b*4 + w)*512 + n] = 1.f/(1.f + expf(-logit));
    }
}

// ---------------- driver ----------------
extern "C" void kernel_launch(void* const* d_in, const int* in_sizes, int n_in,
                              void* d_out, int out_size)
{
    (void)in_sizes; (void)n_in; (void)out_size;
    const float* mel     = (const float*)d_in[0];
    const float* patch_w = (const float*)d_in[1];
    const float* patch_b = (const float*)d_in[2];
    const float* pos     = (const float*)d_in[3];
    const float* proj    = (const float*)d_in[4];
    const float* ln1_s   = (const float*)d_in[5];
    const float* ln1_b   = (const float*)d_in[6];
    const float* qkv_w   = (const float*)d_in[7];
    const float* qkv_b   = (const float*)d_in[8];
    const float* ao_w    = (const float*)d_in[9];
    const float* ao_b    = (const float*)d_in[10];
    const float* ln2_s   = (const float*)d_in[11];
    const float* ln2_b   = (const float*)d_in[12];
    const float* ff1_w   = (const float*)d_in[13];
    const float* ff1_b   = (const float*)d_in[14];
    const float* ff2_w   = (const float*)d_in[15];
    const float* ff2_b   = (const float*)d_in[16];
    const float* mask_w  = (const float*)d_in[17];
    const float* mask_b  = (const float*)d_in[18];
    float* out = (float*)d_out;

    float *x, *lnb, *qkv, *ffb, *uq, *uk, *ctxb, *attn, *diag, *ps, *den, *im2, *pwT;
    cudaGetSymbolAddress((void**)&x,    g_x);
    cudaGetSymbolAddress((void**)&lnb,  g_lnbuf);
    cudaGetSymbolAddress((void**)&qkv,  g_qkv);
    cudaGetSymbolAddress((void**)&ffb,  g_ffbuf);
    cudaGetSymbolAddress((void**)&uq,   g_uq);
    cudaGetSymbolAddress((void**)&uk,   g_uk);
    cudaGetSymbolAddress((void**)&ctxb, g_ctxb);
    cudaGetSymbolAddress((void**)&attn, g_attn);
    cudaGetSymbolAddress((void**)&diag, g_diag);
    cudaGetSymbolAddress((void**)&ps,   g_pksum);
    cudaGetSymbolAddress((void**)&den,  g_den);
    cudaGetSymbolAddress((void**)&im2,  g_im2col);
    cudaGetSymbolAddress((void**)&pwT,  g_pwT);

    // patch embed: im2col + GEMM(4096x256 @ 256x768) + bias + pos embed
    im2col_kernel<<<4096, 256>>>(mel, im2);
    transpose_pw<<<768, 256>>>(patch_w, pwT);
    gemm128<<<dim3(6, 32), 256>>>(im2, pwT, patch_b, x, 256, 768, 3, pos);

    for (int l = 0; l < NDEPTH; l++){
        ln_kernel<<<4096, 256>>>(x, ln1_s + l*768, ln1_b + l*768, lnb);
        gemm128<<<dim3(18, 32), 256>>>(lnb, qkv_w + (size_t)l*768*2304,
                                       qkv_b + l*2304, qkv, 768, 2304, 0, 0);
        diag_kernel<<<8192, 256>>>(qkv, diag);
        phi_u_kernel<<<dim3(4, 8, 64), 256>>>(qkv, proj, uq, 0, 0);
        phi_u_kernel<<<dim3(4, 8, 64), 256>>>(qkv, proj, uk, 768, 1);
        pq_fin<<<4096, 256>>>(uq, diag);
        pk_fin<<<32768, 256>>>(uk, diag + 32768);
        pksum_kernel<<<64, 256>>>(uk, ps);
        den_kernel<<<4096, 256>>>(uq, ps, den);
        ctx_kernel<<<dim3(4, 64), 256>>>(uk, qkv, ctxb);
        attn_out_kernel<<<dim3(8, 64), 256>>>(uq, ctxb, den, attn);
        gemm128<<<dim3(6, 32), 256>>>(attn, ao_w + (size_t)l*768*768,
                                      ao_b + l*768, x, 768, 768, 2, 0);
        ln_kernel<<<4096, 256>>>(x, ln2_s + l*768, ln2_b + l*768, lnb);
        gemm128<<<dim3(24, 32), 256>>>(lnb, ff1_w + (size_t)l*768*3072,
                                       ff1_b + l*3072, ffb, 768, 3072, 1, 0);
        gemm128<<<dim3(6, 32), 256>>>(ffb, ff2_w + (size_t)l*3072*768,
                                      ff2_b + l*768, x, 3072, 768, 2, 0);
    }

    mask_kernel<<<4096, 128>>>(x, mask_w, mask_b, out);
}

// round 3
// speedup vs baseline: 2.4312x; 2.4312x over previous
#include <cuda_runtime.h>
#include <math.h>
#include <stdint.h>

#define TOK    4096   // B*N tokens
#define DMODEL 768
#define NSEQ   512
#define NHEAD  8
#define DHEAD  96
#define NFEAT  256
#define NBH    64     // B*H
#define NFF    3072
#define NDEPTH 6

// ---------------- scratch (device globals; no allocations) ----------------
__device__ float g_x[TOK*DMODEL];
__device__ float g_lnbuf[TOK*DMODEL];
__device__ float g_qkv[TOK*3*DMODEL];
__device__ float g_ffbuf[TOK*NFF];
__device__ float g_uq[NBH*NSEQ*NFEAT];
__device__ float g_uk[NBH*NSEQ*NFEAT];
__device__ float g_ctxb[NBH*NFEAT*DHEAD];
__device__ float g_attn[TOK*DMODEL];
__device__ float g_diag[2*NBH*NSEQ];
__device__ float g_pksum[NBH*NFEAT];
__device__ float g_den[NBH*NSEQ];
__device__ float g_im2col[TOK*256];
__device__ float g_pwT[DMODEL*256];        // rounded patch_w as [768][256] (N-major, K contig)
__device__ unsigned g_kmax;
// transposed (to [N][K], tf32-rounded) weights
__device__ float g_wt_qkv[NDEPTH*2304*768];
__device__ float g_wt_ao [NDEPTH*768*768];
__device__ float g_wt_ff1[NDEPTH*3072*768];
__device__ float g_wt_ff2[NDEPTH*768*3072];

// ---------------- helpers ----------------
__device__ __forceinline__ unsigned enc_f(float f){
    unsigned u = __float_as_uint(f);
    return (u & 0x80000000u) ? ~u : (u | 0x80000000u);
}
__device__ __forceinline__ float dec_f(unsigned e){
    return (e & 0x80000000u) ? __uint_as_float(e ^ 0x80000000u) : __uint_as_float(~e);
}
__device__ __forceinline__ float wsum(float v){
    #pragma unroll
    for (int o = 16; o > 0; o >>= 1) v += __shfl_xor_sync(0xffffffffu, v, o);
    return v;
}
__device__ __forceinline__ float wmax(float v){
    #pragma unroll
    for (int o = 16; o > 0; o >>= 1) v = fmaxf(v, __shfl_xor_sync(0xffffffffu, v, o));
    return v;
}
__device__ __forceinline__ float rtf32(float x){
    uint32_t o; asm("cvt.rna.tf32.f32 %0, %1;" : "=r"(o) : "f"(x));
    return __uint_as_float(o);
}
__device__ __forceinline__ uint32_t smem_u32(const void* p){
    uint32_t a;
    asm("{ .reg .u64 t; cvta.to.shared.u64 t, %1; cvt.u32.u64 %0, t; }" : "=r"(a) : "l"(p));
    return a;
}
__device__ __forceinline__ void mma_tf32(float* c, const float* a, const float* b){
    asm volatile(
        "mma.sync.aligned.m16n8k8.row.col.f32.tf32.tf32.f32 "
        "{%0,%1,%2,%3}, {%4,%5,%6,%7}, {%8,%9}, {%0,%1,%2,%3};"
        : "+f"(c[0]), "+f"(c[1]), "+f"(c[2]), "+f"(c[3])
        : "r"(__float_as_uint(a[0])), "r"(__float_as_uint(a[1])),
          "r"(__float_as_uint(a[2])), "r"(__float_as_uint(a[3])),
          "r"(__float_as_uint(b[0])), "r"(__float_as_uint(b[1])));
}

// ---------------- tf32 mma.sync GEMM: C[4096,N] = A[4096,K] @ WT[N,K]^T ----------------
// block tile 128x128, 4 warps (2x2), warp tile 64x64, BK=32, 3-stage cp.async.
// smem: per stage: A[128][36] + B[128][36] floats (stride 36 -> conflict-free frags)
// ep: 0 bias | 1 gelu(bias)+tf32round | 2 +=residual | 3 +pos-embed
#define SSTRIDE 36
#define STAGEF  (2*128*SSTRIDE)          // floats per stage
#define GEMM_SMEM (3*STAGEF*4)           // bytes
__global__ void __launch_bounds__(128, 1) gemm_tc(
    const float* __restrict__ A, const float* __restrict__ WT,
    const float* __restrict__ bias, float* __restrict__ C,
    int K, int Ncols, int ep, const float* __restrict__ aux)
{
    extern __shared__ float sm[];
    int tid = threadIdx.x, lane = tid & 31, wid = tid >> 5;
    int wm = wid & 1, wn = wid >> 1;     // 2x2 warp grid
    int n0 = blockIdx.x*128, m0 = blockIdx.y*128;
    int NC = K >> 5;
    uint32_t sb = smem_u32(sm);

    auto ldstage = [&](int s, int c){
        uint32_t abase = sb + (uint32_t)s*STAGEF*4;
        const float* Ag = A  + (size_t)m0*K + c*32;
        const float* Bg = WT + (size_t)n0*K + c*32;
        #pragma unroll
        for (int i = 0; i < 8; i++){
            int p = tid + i*128; int r = p >> 3, c4 = p & 7;
            uint32_t off = (uint32_t)(r*SSTRIDE + c4*4)*4;
            asm volatile("cp.async.cg.shared.global [%0], [%1], 16;"
                         :: "r"(abase + off), "l"(Ag + (size_t)r*K + c4*4));
        }
        #pragma unroll
        for (int i = 0; i < 8; i++){
            int p = tid + i*128; int r = p >> 3, c4 = p & 7;
            uint32_t off = (uint32_t)(128*SSTRIDE + r*SSTRIDE + c4*4)*4;
            asm volatile("cp.async.cg.shared.global [%0], [%1], 16;"
                         :: "r"(abase + off), "l"(Bg + (size_t)r*K + c4*4));
        }
        asm volatile("cp.async.commit_group;");
    };

    float acc[4][8][4];
    #pragma unroll
    for (int mt = 0; mt < 4; mt++)
        #pragma unroll
        for (int nt = 0; nt < 8; nt++)
            #pragma unroll
            for (int r = 0; r < 4; r++) acc[mt][nt][r] = 0.f;

    // prologue: 3 stages
    ldstage(0, 0); ldstage(1, 1); ldstage(2, 2);

    int lq = lane >> 2, lr = lane & 3;

    for (int c = 0; c < NC; c++){
        int pend = NC - 1 - c;
        if (pend >= 2)      asm volatile("cp.async.wait_group 2;" ::: "memory");
        else if (pend == 1) asm volatile("cp.async.wait_group 1;" ::: "memory");
        else                asm volatile("cp.async.wait_group 0;" ::: "memory");
        __syncthreads();

        const float* As = sm + (c % 3)*STAGEF;
        const float* Bs = As + 128*SSTRIDE;

        #pragma unroll
        for (int k8 = 0; k8 < 4; k8++){
            int kb = k8*8 + lr;
            float a[4][4], b[8][2];
            int ar = wm*64 + lq;
            #pragma unroll
            for (int mt = 0; mt < 4; mt++){
                const float* p0 = As + (size_t)(ar + mt*16)*SSTRIDE + kb;
                const float* p1 = As + (size_t)(ar + mt*16 + 8)*SSTRIDE + kb;
                a[mt][0] = p0[0]; a[mt][1] = p1[0];
                a[mt][2] = p0[4]; a[mt][3] = p1[4];
            }
            int br = wn*64 + lq;
            #pragma unroll
            for (int nt = 0; nt < 8; nt++){
                const float* p = Bs + (size_t)(br + nt*8)*SSTRIDE + kb;
                b[nt][0] = p[0]; b[nt][1] = p[4];
            }
            #pragma unroll
            for (int mt = 0; mt < 4; mt++)
                #pragma unroll
                for (int nt = 0; nt < 8; nt++)
                    mma_tf32(acc[mt][nt], a[mt], b[nt]);
        }
        __syncthreads();
        if (c + 3 < NC) ldstage(c % 3, c + 3);
    }

    // epilogue
    int row_base = m0 + wm*64 + lq;
    int col_base = n0 + wn*64 + lr*2;
    #pragma unroll
    for (int mt = 0; mt < 4; mt++){
        #pragma unroll
        for (int h = 0; h < 2; h++){
            int row = row_base + mt*16 + h*8;
            float* crow = C + (size_t)row*Ncols;
            const float* arow = aux ? (aux + (size_t)(row & 511)*DMODEL) : (const float*)0;
            #pragma unroll
            for (int nt = 0; nt < 8; nt++){
                int col = col_base + nt*8;
                float v0 = acc[mt][nt][h*2+0] + bias[col];
                float v1 = acc[mt][nt][h*2+1] + bias[col+1];
                if (ep == 1){
                    v0 = rtf32(0.5f*v0*(1.0f + erff(v0*0.70710678118654752f)));
                    v1 = rtf32(0.5f*v1*(1.0f + erff(v1*0.70710678118654752f)));
                } else if (ep == 2){
                    float2 old = *(const float2*)(crow + col);
                    v0 += old.x; v1 += old.y;
                } else if (ep == 3){
                    v0 += arow[col]; v1 += arow[col+1];
                }
                float2 o; o.x = v0; o.y = v1;
                *(float2*)(crow + col) = o;
            }
        }
    }
}

// ---------------- weight transpose [K][N] -> [N][K] with tf32 rounding ----------------
__global__ void transpose_w(const float* __restrict__ src, float* __restrict__ dst,
                            int K, int N)
{
    __shared__ float t[32][33];
    int n0 = blockIdx.x*32, k0 = blockIdx.y*32;
    size_t off = (size_t)blockIdx.z * (size_t)K * N;
    src += off; dst += off;
    int tx = threadIdx.x & 31, ty = threadIdx.x >> 5;
    #pragma unroll
    for (int i = 0; i < 32; i += 8)
        t[ty+i][tx] = src[(size_t)(k0+ty+i)*N + n0+tx];
    __syncthreads();
    #pragma unroll
    for (int i = 0; i < 32; i += 8)
        dst[(size_t)(n0+ty+i)*K + k0+tx] = rtf32(t[tx][ty+i]);
}

__global__ void copy_round(const float* __restrict__ src, float* __restrict__ dst){
    int i = blockIdx.x*256 + threadIdx.x;
    dst[i] = rtf32(src[i]);
}

// ---------------- patch embed prep ----------------
__global__ void im2col_kernel(const float* __restrict__ mel, float* __restrict__ dst){
    int idx = blockIdx.x*256 + threadIdx.x;
    int pg = idx >> 8, k = idx & 255;
    int b = pg >> 9, p = pg & 511;
    int oh = p >> 3, ow = p & 7;
    int i = k >> 4, j = k & 15;
    dst[idx] = rtf32(mel[(size_t)b*131072 + (size_t)(oh*16 + i)*128 + ow*16 + j]);
}

// ---------------- layernorm (tf32-rounded output -> GEMM input) ----------------
__global__ void ln_kernel(const float* __restrict__ X, const float* __restrict__ sc,
                          const float* __restrict__ bb, float* __restrict__ Y)
{
    __shared__ float s1[8], s2[8];
    int row = blockIdx.x, tid = threadIdx.x;
    int lane = tid & 31, wid = tid >> 5;
    const float* xr = X + (size_t)row*DMODEL;
    float v[3]; float sum = 0.f, sq = 0.f;
    #pragma unroll
    for (int i = 0; i < 3; i++){
        v[i] = xr[tid + 256*i];
        sum += v[i]; sq += v[i]*v[i];
    }
    sum = wsum(sum); sq = wsum(sq);
    if (lane == 0){ s1[wid] = sum; s2[wid] = sq; }
    __syncthreads();
    if (tid == 0){
        float a = 0.f, b2 = 0.f;
        #pragma unroll
        for (int i = 0; i < 8; i++){ a += s1[i]; b2 += s2[i]; }
        s1[0] = a; s2[0] = b2;
    }
    __syncthreads();
    float mean = s1[0]*(1.f/768.f);
    float var  = s2[0]*(1.f/768.f) - mean*mean;
    float rstd = rsqrtf(var + 1e-5f);
    float* yr = Y + (size_t)row*DMODEL;
    #pragma unroll
    for (int i = 0; i < 3; i++){
        int d = tid + 256*i;
        yr[d] = rtf32((v[i] - mean)*rstd*sc[d] + bb[d]);
    }
}

// ---------------- FAVOR+ pieces (SIMT) ----------------
__global__ void diag_kernel(const float* __restrict__ qkv, float* __restrict__ diag)
{
    if (blockIdx.x == 0 && threadIdx.x == 0) g_kmax = 0u;
    int gw = blockIdx.x*8 + (threadIdx.x >> 5);
    int lane = threadIdx.x & 31;
    int which = gw >> 15;
    int r = gw & 32767;
    int bh = r >> 9, n = r & 511;
    int b = bh >> 3, h = bh & 7;
    const float* p = qkv + (size_t)(b*512 + n)*2304 + which*768 + h*96;
    float s = 0.f;
    #pragma unroll
    for (int i = 0; i < 3; i++){ float t = p[lane + 32*i]; s += t*t; }
    s = wsum(s);
    if (lane == 0) diag[gw] = 0.05103103631f * s;
}

__global__ __launch_bounds__(256) void phi_u_kernel(
    const float* __restrict__ qkv, const float* __restrict__ proj,
    float* __restrict__ U, int off, int isk)
{
    __shared__ __align__(16) float Qs[16][68];
    __shared__ __align__(16) float Ps[16][68];
    __shared__ float red[256];
    int bh = blockIdx.z, b = bh >> 3, h = bh & 7;
    int n0 = blockIdx.y*64, m0 = blockIdx.x*64;
    int tid = threadIdx.x, tx = tid & 15, ty = tid >> 4;
    const float* Abase = qkv + (size_t)(b*512)*2304 + off + h*96;

    float acc[4][4];
    #pragma unroll
    for (int i = 0; i < 4; i++)
        #pragma unroll
        for (int j = 0; j < 4; j++) acc[i][j] = 0.f;

    for (int k0 = 0; k0 < 96; k0 += 16){
        {
            int r = tid >> 2, c4 = tid & 3;
            float4 v = *(const float4*)(Abase + (size_t)(n0 + r)*2304 + k0 + c4*4);
            Qs[c4*4+0][r] = v.x; Qs[c4*4+1][r] = v.y;
            Qs[c4*4+2][r] = v.z; Qs[c4*4+3][r] = v.w;
        }
        {
            int r = tid >> 2, c4 = tid & 3;
            float4 v = *(const float4*)(proj + (size_t)(m0 + r)*96 + k0 + c4*4);
            Ps[c4*4+0][r] = v.x; Ps[c4*4+1][r] = v.y;
            Ps[c4*4+2][r] = v.z; Ps[c4*4+3][r] = v.w;
        }
        __syncthreads();
        #pragma unroll
        for (int kk = 0; kk < 16; kk++){
            float a[4], bv[4];
            *(float4*)a  = *(const float4*)(&Qs[kk][ty*4]);
            *(float4*)bv = *(const float4*)(&Ps[kk][tx*4]);
            #pragma unroll
            for (int i = 0; i < 4; i++)
                #pragma unroll
                for (int j = 0; j < 4; j++)
                    acc[i][j] = fmaf(a[i], bv[j], acc[i][j]);
        }
        __syncthreads();
    }

    const float cs = 0.31947155f;
    float tmax = -1e30f;
    float* Ub = U + ((size_t)bh*512 + n0)*256 + m0;
    #pragma unroll
    for (int i = 0; i < 4; i++)
        #pragma unroll
        for (int j = 0; j < 4; j++){
            float u = acc[i][j]*cs;
            Ub[(size_t)(ty*4 + i)*256 + tx*4 + j] = u;
            tmax = fmaxf(tmax, u);
        }
    if (isk){
        red[tid] = tmax;
        __syncthreads();
        for (int s = 128; s > 0; s >>= 1){
            if (tid < s) red[tid] = fmaxf(red[tid], red[tid + s]);
            __syncthreads();
        }
        if (tid == 0) atomicMax(&g_kmax, enc_f(red[0]));
    }
}

__global__ void pq_fin(float* __restrict__ U, const float* __restrict__ diagq)
{
    int gw = blockIdx.x*8 + (threadIdx.x >> 5);
    int lane = threadIdx.x & 31;
    float* u = U + (size_t)gw*256;
    float v[8]; float m = -1e30f;
    #pragma unroll
    for (int i = 0; i < 8; i++){ v[i] = u[lane + 32*i]; m = fmaxf(m, v[i]); }
    m = wmax(m);
    float d = diagq[gw];
    #pragma unroll
    for (int i = 0; i < 8; i++)
        u[lane + 32*i] = (expf(v[i] - d - m) + 1e-4f)*0.0625f;
}

__global__ void pk_fin(float* __restrict__ U, const float* __restrict__ diagk)
{
    float kst = dec_f(g_kmax);
    int i = blockIdx.x*256 + threadIdx.x;
    float v = U[i];
    int r = i >> 8;
    U[i] = (expf(v - diagk[r] - kst) + 1e-4f)*0.0625f;
}

__global__ void pksum_kernel(const float* __restrict__ pk, float* __restrict__ ps)
{
    int bh = blockIdx.x, m = threadIdx.x;
    const float* p = pk + (size_t)bh*512*256 + m;
    float s = 0.f;
    for (int n = 0; n < 512; n++) s += p[(size_t)n*256];
    ps[bh*256 + m] = s;
}

__global__ void den_kernel(const float* __restrict__ pq, const float* __restrict__ ps,
                           float* __restrict__ den)
{
    int gw = blockIdx.x*8 + (threadIdx.x >> 5);
    int lane = threadIdx.x & 31;
    int bh = gw >> 9;
    const float* q = pq + (size_t)gw*256;
    const float* s = ps + bh*256;
    float a = 0.f;
    #pragma unroll
    for (int i = 0; i < 8; i++){ int j = lane + 32*i; a += q[j]*s[j]; }
    a = wsum(a);
    if (lane == 0) den[gw] = a;
}

__global__ __launch_bounds__(256) void ctx_kernel(
    const float* __restrict__ pk, const float* __restrict__ qkv, float* __restrict__ ctx)
{
    __shared__ __align__(16) float Ks[16][64];
    __shared__ float Vs[16][96];
    int bh = blockIdx.y, b = bh >> 3, h = bh & 7;
    int m0 = blockIdx.x*64;
    int tid = threadIdx.x, tx = tid & 15, ty = tid >> 4;
    const float* vbase = qkv + (size_t)(b*512)*2304 + 1536 + h*96;

    float acc[4][6];
    #pragma unroll
    for (int i = 0; i < 4; i++)
        #pragma unroll
        for (int j = 0; j < 6; j++) acc[i][j] = 0.f;

    for (int n0 = 0; n0 < 512; n0 += 16){
        {
            int r = tid >> 4, c4 = tid & 15;
            *(float4*)&Ks[r][c4*4] =
                *(const float4*)(pk + ((size_t)bh*512 + n0 + r)*256 + m0 + c4*4);
        }
        #pragma unroll
        for (int i = 0; i < 6; i++){
            int s = tid + i*256;
            int r = s/96, c = s - r*96;
            Vs[r][c] = vbase[(size_t)(n0 + r)*2304 + c];
        }
        __syncthreads();
        #pragma unroll
        for (int kk = 0; kk < 16; kk++){
            float a[4];
            *(float4*)a = *(const float4*)(&Ks[kk][ty*4]);
            float bv[6];
            #pragma unroll
            for (int j = 0; j < 6; j++) bv[j] = Vs[kk][tx*6 + j];
            #pragma unroll
            for (int i = 0; i < 4; i++)
                #pragma unroll
                for (int j = 0; j < 6; j++)
                    acc[i][j] = fmaf(a[i], bv[j], acc[i][j]);
        }
        __syncthreads();
    }
    #pragma unroll
    for (int i = 0; i < 4; i++)
        #pragma unroll
        for (int j = 0; j < 6; j++)
            ctx[(size_t)bh*24576 + (size_t)(m0 + ty*4 + i)*96 + tx*6 + j] = acc[i][j];
}

__global__ __launch_bounds__(256) void attn_out_kernel(
    const float* __restrict__ pq, const float* __restrict__ ctx,
    const float* __restrict__ den, float* __restrict__ attn)
{
    __shared__ __align__(16) float Qs[16][64];
    __shared__ float Cs[16][96];
    int bh = blockIdx.y, b = bh >> 3, h = bh & 7;
    int n0 = blockIdx.x*64;
    int tid = threadIdx.x, tx = tid & 15, ty = tid >> 4;

    float acc[4][6];
    #pragma unroll
    for (int i = 0; i < 4; i++)
        #pragma unroll
        for (int j = 0; j < 6; j++) acc[i][j] = 0.f;

    for (int k0 = 0; k0 < 256; k0 += 16){
        {
            int r = tid >> 2, c4 = tid & 3;
            float4 v = *(const float4*)(pq + ((size_t)bh*512 + n0 + r)*256 + k0 + c4*4);
            Qs[c4*4+0][r] = v.x; Qs[c4*4+1][r] = v.y;
            Qs[c4*4+2][r] = v.z; Qs[c4*4+3][r] = v.w;
        }
        #pragma unroll
        for (int i = 0; i < 6; i++){
            int s = tid + i*256;
            int r = s/96, c = s - r*96;
            Cs[r][c] = ctx[(size_t)bh*24576 + (size_t)(k0 + r)*96 + c];
        }
        __syncthreads();
        #pragma unroll
        for (int kk = 0; kk < 16; kk++){
            float a[4];
            *(float4*)a = *(const float4*)(&Qs[kk][ty*4]);
            float bv[6];
            #pragma unroll
            for (int j = 0; j < 6; j++) bv[j] = Cs[kk][tx*6 + j];
            #pragma unroll
            for (int i = 0; i < 4; i++)
                #pragma unroll
                for (int j = 0; j < 6; j++)
                    acc[i][j] = fmaf(a[i], bv[j], acc[i][j]);
        }
        __syncthreads();
    }
    #pragma unroll
    for (int i = 0; i < 4; i++){
        int n = n0 + ty*4 + i;
        float dinv = 1.f/den[bh*512 + n];
        #pragma unroll
        for (int j = 0; j < 6; j++)
            attn[(size_t)(b*512 + n)*768 + h*96 + tx*6 + j] = rtf32(acc[i][j]*dinv);
    }
}

// ---------------- mask head ----------------
__global__ void mask_kernel(const float* __restrict__ X, const float* __restrict__ mw,
                            const float* __restrict__ mb, float* __restrict__ out)
{
    int row = blockIdx.x;
    int tid = threadIdx.x;
    int w = tid >> 5, lane = tid & 31;
    const float* xr = X + (size_t)row*768;
    float s = 0.f;
    for (int d = lane; d < 768; d += 32) s += xr[d]*mw[d*4 + w];
    s = wsum(s);
    if (lane == 0){
        float logit = s + mb[w];
        int b = row >> 9, n = row & 511;
        out[((size_t)b*4 + w)*512 + n] = 1.f/(1.f + expf(-logit));
    }
}

// ---------------- driver ----------------
extern "C" void kernel_launch(void* const* d_in, const int* in_sizes, int n_in,
                              void* d_out, int out_size)
{
    (void)in_sizes; (void)n_in; (void)out_size;
    const float* mel     = (const float*)d_in[0];
    const float* patch_w = (const float*)d_in[1];
    const float* patch_b = (const float*)d_in[2];
    const float* pos     = (const float*)d_in[3];
    const float* proj    = (const float*)d_in[4];
    const float* ln1_s   = (const float*)d_in[5];
    const float* ln1_b   = (const float*)d_in[6];
    const float* qkv_w   = (const float*)d_in[7];
    const float* qkv_b   = (const float*)d_in[8];
    const float* ao_w    = (const float*)d_in[9];
    const float* ao_b    = (const float*)d_in[10];
    const float* ln2_s   = (const float*)d_in[11];
    const float* ln2_b   = (const float*)d_in[12];
    const float* ff1_w   = (const float*)d_in[13];
    const float* ff1_b   = (const float*)d_in[14];
    const float* ff2_w   = (const float*)d_in[15];
    const float* ff2_b   = (const float*)d_in[16];
    const float* mask_w  = (const float*)d_in[17];
    const float* mask_b  = (const float*)d_in[18];
    float* out = (float*)d_out;

    float *x, *lnb, *qkv, *ffb, *uq, *uk, *ctxb, *attn, *diag, *ps, *den, *im2, *pwT;
    float *wtq, *wtao, *wtf1, *wtf2;
    cudaGetSymbolAddress((void**)&x,    g_x);
    cudaGetSymbolAddress((void**)&lnb,  g_lnbuf);
    cudaGetSymbolAddress((void**)&qkv,  g_qkv);
    cudaGetSymbolAddress((void**)&ffb,  g_ffbuf);
    cudaGetSymbolAddress((void**)&uq,   g_uq);
    cudaGetSymbolAddress((void**)&uk,   g_uk);
    cudaGetSymbolAddress((void**)&ctxb, g_ctxb);
    cudaGetSymbolAddress((void**)&attn, g_attn);
    cudaGetSymbolAddress((void**)&diag, g_diag);
    cudaGetSymbolAddress((void**)&ps,   g_pksum);
    cudaGetSymbolAddress((void**)&den,  g_den);
    cudaGetSymbolAddress((void**)&im2,  g_im2col);
    cudaGetSymbolAddress((void**)&pwT,  g_pwT);
    cudaGetSymbolAddress((void**)&wtq,  g_wt_qkv);
    cudaGetSymbolAddress((void**)&wtao, g_wt_ao);
    cudaGetSymbolAddress((void**)&wtf1, g_wt_ff1);
    cudaGetSymbolAddress((void**)&wtf2, g_wt_ff2);

    cudaFuncSetAttribute(gemm_tc, cudaFuncAttributeMaxDynamicSharedMemorySize, GEMM_SMEM);

    // weight prep: transpose [K][N] -> [N][K], tf32-rounded
    copy_round<<<768, 256>>>(patch_w, pwT);
    transpose_w<<<dim3(72, 24, 6), 256>>>(qkv_w, wtq, 768, 2304);
    transpose_w<<<dim3(24, 24, 6), 256>>>(ao_w,  wtao, 768, 768);
    transpose_w<<<dim3(96, 24, 6), 256>>>(ff1_w, wtf1, 768, 3072);
    transpose_w<<<dim3(24, 96, 6), 256>>>(ff2_w, wtf2, 3072, 768);

    // patch embed
    im2col_kernel<<<4096, 256>>>(mel, im2);
    gemm_tc<<<dim3(6, 32), 128, GEMM_SMEM>>>(im2, pwT, patch_b, x, 256, 768, 3, pos);

    for (int l = 0; l < NDEPTH; l++){
        ln_kernel<<<4096, 256>>>(x, ln1_s + l*768, ln1_b + l*768, lnb);
        gemm_tc<<<dim3(18, 32), 128, GEMM_SMEM>>>(
            lnb, wtq + (size_t)l*2304*768, qkv_b + l*2304, qkv, 768, 2304, 0, 0);
        diag_kernel<<<8192, 256>>>(qkv, diag);
        phi_u_kernel<<<dim3(4, 8, 64), 256>>>(qkv, proj, uq, 0, 0);
        phi_u_kernel<<<dim3(4, 8, 64), 256>>>(qkv, proj, uk, 768, 1);
        pq_fin<<<4096, 256>>>(uq, diag);
        pk_fin<<<32768, 256>>>(uk, diag + 32768);
        pksum_kernel<<<64, 256>>>(uk, ps);
        den_kernel<<<4096, 256>>>(uq, ps, den);
        ctx_kernel<<<dim3(4, 64), 256>>>(uk, qkv, ctxb);
        attn_out_kernel<<<dim3(8, 64), 256>>>(uq, ctxb, den, attn);
        gemm_tc<<<dim3(6, 32), 128, GEMM_SMEM>>>(
            attn, wtao + (size_t)l*768*768, ao_b + l*768, x, 768, 768, 2, 0);
        ln_kernel<<<4096, 256>>>(x, ln2_s + l*768, ln2_b + l*768, lnb);
        gemm_tc<<<dim3(24, 32), 128, GEMM_SMEM>>>(
            lnb, wtf1 + (size_t)l*768*3072, ff1_b + l*3072, ffb, 768, 3072, 1, 0);
        gemm_tc<<<dim3(6, 32), 128, GEMM_SMEM>>>(
            ffb, wtf2 + (size_t)l*3072*768, ff2_b + l*768, x, 3072, 768, 2, 0);
    }

    mask_kernel<<<4096, 128>>>(x, mask_w, mask_b, out);
}

// round 4
// speedup vs baseline: 2.9700x; 1.2216x over previous
#include <cuda_runtime.h>
#include <math.h>
#include <stdint.h>

#define TOK    4096   // B*N tokens
#define DMODEL 768
#define NSEQ   512
#define NHEAD  8
#define DHEAD  96
#define NFEAT  256
#define NBH    64     // B*H
#define NFF    3072
#define NDEPTH 6

// ---------------- scratch (device globals; no allocations) ----------------
__device__ float g_x[TOK*DMODEL];
__device__ float g_lnbuf[TOK*DMODEL];
__device__ float g_qkv[TOK*3*DMODEL];
__device__ float g_ffbuf[TOK*NFF];
__device__ float g_uq[NBH*NSEQ*NFEAT];
__device__ float g_uk[NBH*NSEQ*NFEAT];
__device__ float g_ctxb[NBH*DHEAD*NFEAT];   // ctxT [bh][96e][256m]
__device__ float g_attn[TOK*DMODEL];
__device__ float g_diag[2*NBH*NSEQ];
__device__ float g_pksum[NBH*NFEAT];
__device__ float g_den[NBH*NSEQ];
__device__ float g_im2col[TOK*256];
__device__ float g_pwT[DMODEL*256];
__device__ unsigned g_kmax;
// transposed (to [N][K], tf32-rounded) weights
__device__ float g_wt_qkv[NDEPTH*2304*768];
__device__ float g_wt_ao [NDEPTH*768*768];
__device__ float g_wt_ff1[NDEPTH*3072*768];
__device__ float g_wt_ff2[NDEPTH*768*3072];

// ---------------- helpers ----------------
__device__ __forceinline__ unsigned enc_f(float f){
    unsigned u = __float_as_uint(f);
    return (u & 0x80000000u) ? ~u : (u | 0x80000000u);
}
__device__ __forceinline__ float dec_f(unsigned e){
    return (e & 0x80000000u) ? __uint_as_float(e ^ 0x80000000u) : __uint_as_float(~e);
}
__device__ __forceinline__ float wsum(float v){
    #pragma unroll
    for (int o = 16; o > 0; o >>= 1) v += __shfl_xor_sync(0xffffffffu, v, o);
    return v;
}
__device__ __forceinline__ float wmax(float v){
    #pragma unroll
    for (int o = 16; o > 0; o >>= 1) v = fmaxf(v, __shfl_xor_sync(0xffffffffu, v, o));
    return v;
}
__device__ __forceinline__ float rtf32(float x){
    uint32_t o; asm("cvt.rna.tf32.f32 %0, %1;" : "=r"(o) : "f"(x));
    return __uint_as_float(o);
}
__device__ __forceinline__ uint32_t smem_u32(const void* p){
    uint32_t a;
    asm("{ .reg .u64 t; cvta.to.shared.u64 t, %1; cvt.u32.u64 %0, t; }" : "=r"(a) : "l"(p));
    return a;
}
__device__ __forceinline__ void mma_tf32(float* c, const float* a, const float* b){
    asm volatile(
        "mma.sync.aligned.m16n8k8.row.col.f32.tf32.tf32.f32 "
        "{%0,%1,%2,%3}, {%4,%5,%6,%7}, {%8,%9}, {%0,%1,%2,%3};"
        : "+f"(c[0]), "+f"(c[1]), "+f"(c[2]), "+f"(c[3])
        : "r"(__float_as_uint(a[0])), "r"(__float_as_uint(a[1])),
          "r"(__float_as_uint(a[2])), "r"(__float_as_uint(a[3])),
          "r"(__float_as_uint(b[0])), "r"(__float_as_uint(b[1])));
}
#define CPA16(saddr, gptr) \
    asm volatile("cp.async.cg.shared.global [%0], [%1], 16;" :: "r"(saddr), "l"(gptr))

// ---------------- tf32 mma.sync GEMM: C[4096,N] = A[4096,K] @ WT[N,K]^T ----------------
#define SSTRIDE 36
#define STAGEF  (2*128*SSTRIDE)
#define GEMM_SMEM (3*STAGEF*4)
__global__ void __launch_bounds__(128, 1) gemm_tc(
    const float* __restrict__ A, const float* __restrict__ WT,
    const float* __restrict__ bias, float* __restrict__ C,
    int K, int Ncols, int ep, const float* __restrict__ aux)
{
    extern __shared__ float sm[];
    int tid = threadIdx.x, lane = tid & 31, wid = tid >> 5;
    int wm = wid & 1, wn = wid >> 1;
    int n0 = blockIdx.x*128, m0 = blockIdx.y*128;
    int NC = K >> 5;
    uint32_t sb = smem_u32(sm);

    auto ldstage = [&](int s, int c){
        uint32_t abase = sb + (uint32_t)s*STAGEF*4;
        const float* Ag = A  + (size_t)m0*K + c*32;
        const float* Bg = WT + (size_t)n0*K + c*32;
        #pragma unroll
        for (int i = 0; i < 8; i++){
            int p = tid + i*128; int r = p >> 3, c4 = p & 7;
            CPA16(abase + (uint32_t)(r*SSTRIDE + c4*4)*4, Ag + (size_t)r*K + c4*4);
        }
        #pragma unroll
        for (int i = 0; i < 8; i++){
            int p = tid + i*128; int r = p >> 3, c4 = p & 7;
            CPA16(abase + (uint32_t)(128*SSTRIDE + r*SSTRIDE + c4*4)*4, Bg + (size_t)r*K + c4*4);
        }
        asm volatile("cp.async.commit_group;");
    };

    float acc[4][8][4];
    #pragma unroll
    for (int mt = 0; mt < 4; mt++)
        #pragma unroll
        for (int nt = 0; nt < 8; nt++)
            #pragma unroll
            for (int r = 0; r < 4; r++) acc[mt][nt][r] = 0.f;

    ldstage(0, 0); ldstage(1, 1); ldstage(2, 2);
    int lq = lane >> 2, lr = lane & 3;

    for (int c = 0; c < NC; c++){
        int pend = NC - 1 - c;
        if (pend >= 2)      asm volatile("cp.async.wait_group 2;" ::: "memory");
        else if (pend == 1) asm volatile("cp.async.wait_group 1;" ::: "memory");
        else                asm volatile("cp.async.wait_group 0;" ::: "memory");
        __syncthreads();

        const float* As = sm + (c % 3)*STAGEF;
        const float* Bs = As + 128*SSTRIDE;

        #pragma unroll
        for (int k8 = 0; k8 < 4; k8++){
            int kb = k8*8 + lr;
            float a[4][4], b[8][2];
            int ar = wm*64 + lq;
            #pragma unroll
            for (int mt = 0; mt < 4; mt++){
                const float* p0 = As + (size_t)(ar + mt*16)*SSTRIDE + kb;
                const float* p1 = As + (size_t)(ar + mt*16 + 8)*SSTRIDE + kb;
                a[mt][0] = p0[0]; a[mt][1] = p1[0];
                a[mt][2] = p0[4]; a[mt][3] = p1[4];
            }
            int br = wn*64 + lq;
            #pragma unroll
            for (int nt = 0; nt < 8; nt++){
                const float* p = Bs + (size_t)(br + nt*8)*SSTRIDE + kb;
                b[nt][0] = p[0]; b[nt][1] = p[4];
            }
            #pragma unroll
            for (int mt = 0; mt < 4; mt++)
                #pragma unroll
                for (int nt = 0; nt < 8; nt++)
                    mma_tf32(acc[mt][nt], a[mt], b[nt]);
        }
        __syncthreads();
        if (c + 3 < NC) ldstage(c % 3, c + 3);
    }

    int row_base = m0 + wm*64 + lq;
    int col_base = n0 + wn*64 + lr*2;
    #pragma unroll
    for (int mt = 0; mt < 4; mt++){
        #pragma unroll
        for (int h = 0; h < 2; h++){
            int row = row_base + mt*16 + h*8;
            float* crow = C + (size_t)row*Ncols;
            const float* arow = aux ? (aux + (size_t)(row & 511)*DMODEL) : (const float*)0;
            #pragma unroll
            for (int nt = 0; nt < 8; nt++){
                int col = col_base + nt*8;
                float v0 = acc[mt][nt][h*2+0] + bias[col];
                float v1 = acc[mt][nt][h*2+1] + bias[col+1];
                if (ep == 0){
                    v0 = rtf32(v0); v1 = rtf32(v1);
                } else if (ep == 1){
                    v0 = rtf32(0.5f*v0*(1.0f + erff(v0*0.70710678118654752f)));
                    v1 = rtf32(0.5f*v1*(1.0f + erff(v1*0.70710678118654752f)));
                } else if (ep == 2){
                    float2 old = *(const float2*)(crow + col);
                    v0 += old.x; v1 += old.y;
                } else if (ep == 3){
                    v0 += arow[col]; v1 += arow[col+1];
                }
                float2 o; o.x = v0; o.y = v1;
                *(float2*)(crow + col) = o;
            }
        }
    }
}

// ---------------- phi_u: per bh, U[128n x 128m] tile = cs*(X @ proj^T) ----------------
#define PHI_SMEM (3*2*128*36*4)
__global__ void __launch_bounds__(256, 1) phi_u_mma(
    const float* __restrict__ qkv, const float* __restrict__ proj,
    float* __restrict__ U, int off, int isk)
{
    extern __shared__ float sm[];
    __shared__ float red[8];
    int tid = threadIdx.x, lane = tid & 31, wid = tid >> 5;
    int wm = wid & 3, wn = wid >> 2;         // M split 4 (32), N split 2 (64)
    int m0 = blockIdx.x*128, n0 = blockIdx.y*128, bh = blockIdx.z;
    int b = bh >> 3, h = bh & 7;
    const float* Ab = qkv + (size_t)(b*512 + n0)*2304 + off + h*96;
    const float* Bb = proj + (size_t)m0*96;
    int lq = lane >> 2, lr = lane & 3;
    uint32_t sb = smem_u32(sm);

    #pragma unroll
    for (int c = 0; c < 3; c++){
        uint32_t ab = sb + (uint32_t)c*(2*128*36*4);
        #pragma unroll
        for (int i = 0; i < 4; i++){
            int p = tid + i*256; int r = p >> 3, c4 = p & 7;
            CPA16(ab + (uint32_t)(r*36 + c4*4)*4, Ab + (size_t)r*2304 + c*32 + c4*4);
        }
        #pragma unroll
        for (int i = 0; i < 4; i++){
            int p = tid + i*256; int r = p >> 3, c4 = p & 7;
            CPA16(ab + (uint32_t)(128*36 + r*36 + c4*4)*4, Bb + (size_t)r*96 + c*32 + c4*4);
        }
        asm volatile("cp.async.commit_group;");
    }

    float acc[2][8][4];
    #pragma unroll
    for (int mt = 0; mt < 2; mt++)
        #pragma unroll
        for (int nt = 0; nt < 8; nt++)
            #pragma unroll
            for (int r = 0; r < 4; r++) acc[mt][nt][r] = 0.f;

    #pragma unroll
    for (int c = 0; c < 3; c++){
        if (c == 0)      asm volatile("cp.async.wait_group 2;" ::: "memory");
        else if (c == 1) asm volatile("cp.async.wait_group 1;" ::: "memory");
        else             asm volatile("cp.async.wait_group 0;" ::: "memory");
        __syncthreads();
        const float* As = sm + c*(2*128*36);
        const float* Bs = As + 128*36;
        #pragma unroll
        for (int k8 = 0; k8 < 4; k8++){
            int kb = k8*8 + lr;
            float a[2][4], b[8][2];
            int ar = wm*32 + lq;
            #pragma unroll
            for (int mt = 0; mt < 2; mt++){
                const float* p0 = As + (size_t)(ar + mt*16)*36 + kb;
                const float* p1 = As + (size_t)(ar + mt*16 + 8)*36 + kb;
                a[mt][0] = p0[0]; a[mt][1] = p1[0];
                a[mt][2] = p0[4]; a[mt][3] = p1[4];
            }
            int bc = wn*64 + lq;
            #pragma unroll
            for (int nt = 0; nt < 8; nt++){
                const float* p = Bs + (size_t)(bc + nt*8)*36 + kb;
                b[nt][0] = p[0]; b[nt][1] = p[4];
            }
            #pragma unroll
            for (int mt = 0; mt < 2; mt++)
                #pragma unroll
                for (int nt = 0; nt < 8; nt++)
                    mma_tf32(acc[mt][nt], a[mt], b[nt]);
        }
    }

    const float cs = 0.31947155f;   // 96^{-1/4}
    float tmax = -1e30f;
    #pragma unroll
    for (int mt = 0; mt < 2; mt++){
        int n = n0 + wm*32 + mt*16 + lq;
        int m = m0 + wn*64 + lr*2;
        float* u0 = U + ((size_t)bh*512 + n)*256;
        float* u1 = U + ((size_t)bh*512 + n + 8)*256;
        #pragma unroll
        for (int nt = 0; nt < 8; nt++){
            float v0 = acc[mt][nt][0]*cs, v1 = acc[mt][nt][1]*cs;
            float v2 = acc[mt][nt][2]*cs, v3 = acc[mt][nt][3]*cs;
            float2 p0; p0.x = v0; p0.y = v1;
            float2 p1; p1.x = v2; p1.y = v3;
            *(float2*)(u0 + m + nt*8) = p0;
            *(float2*)(u1 + m + nt*8) = p1;
            tmax = fmaxf(tmax, fmaxf(fmaxf(v0, v1), fmaxf(v2, v3)));
        }
    }
    if (isk){
        tmax = wmax(tmax);
        if (lane == 0) red[wid] = tmax;
        __syncthreads();
        if (tid == 0){
            float m = red[0];
            #pragma unroll
            for (int i = 1; i < 8; i++) m = fmaxf(m, red[i]);
            atomicMax(&g_kmax, enc_f(m));
        }
    }
}

// ---------------- ctxT[bh][96e][256m] = sum_n V[n][e]*pk[n][m] ----------------
#define CTX_SV 104
#define CTX_SP 136
#define CTX_STAGEF (32*CTX_SV + 32*CTX_SP)
#define CTX_SMEM (3*CTX_STAGEF*4)
__global__ void __launch_bounds__(256, 1) ctx_mma(
    const float* __restrict__ pk, const float* __restrict__ qkv,
    float* __restrict__ ctxT)
{
    extern __shared__ float sm[];
    int tid = threadIdx.x, lane = tid & 31, wid = tid >> 5;
    int wm = wid & 1, wn = wid >> 1;         // M(e) split 2 (48), N(m) split 4 (32)
    int m0 = blockIdx.x*128, bh = blockIdx.y;
    int b = bh >> 3, h = bh & 7;
    const float* Vb = qkv + (size_t)(b*512)*2304 + 1536 + h*96;
    const float* Pb = pk + (size_t)(bh*512)*256 + m0;
    int lq = lane >> 2, lr = lane & 3;
    uint32_t sb = smem_u32(sm);

    auto ldstage = [&](int s, int c){
        uint32_t ab = sb + (uint32_t)s*CTX_STAGEF*4;
        #pragma unroll
        for (int i = 0; i < 3; i++){
            int p = tid + i*256; int r = p/24, cc = p - r*24;
            CPA16(ab + (uint32_t)(r*CTX_SV + cc*4)*4, Vb + (size_t)(c*32 + r)*2304 + cc*4);
        }
        #pragma unroll
        for (int i = 0; i < 4; i++){
            int p = tid + i*256; int r = p >> 5, cc = p & 31;
            CPA16(ab + (uint32_t)(32*CTX_SV + r*CTX_SP + cc*4)*4,
                  Pb + (size_t)(c*32 + r)*256 + cc*4);
        }
        asm volatile("cp.async.commit_group;");
    };

    float acc[3][4][4];
    #pragma unroll
    for (int mt = 0; mt < 3; mt++)
        #pragma unroll
        for (int nt = 0; nt < 4; nt++)
            #pragma unroll
            for (int r = 0; r < 4; r++) acc[mt][nt][r] = 0.f;

    ldstage(0, 0); ldstage(1, 1); ldstage(2, 2);

    for (int c = 0; c < 16; c++){
        int pend = 15 - c;
        if (pend >= 2)      asm volatile("cp.async.wait_group 2;" ::: "memory");
        else if (pend == 1) asm volatile("cp.async.wait_group 1;" ::: "memory");
        else                asm volatile("cp.async.wait_group 0;" ::: "memory");
        __syncthreads();
        const float* Vs = sm + (c % 3)*CTX_STAGEF;
        const float* Ps = Vs + 32*CTX_SV;

        #pragma unroll
        for (int k8 = 0; k8 < 4; k8++){
            int kb = k8*8 + lr;
            float a[3][4], bfr[4][2];
            int er = wm*48 + lq;
            #pragma unroll
            for (int mt = 0; mt < 3; mt++){
                a[mt][0] = Vs[(size_t)kb*CTX_SV + er + mt*16];
                a[mt][1] = Vs[(size_t)kb*CTX_SV + er + mt*16 + 8];
                a[mt][2] = Vs[(size_t)(kb+4)*CTX_SV + er + mt*16];
                a[mt][3] = Vs[(size_t)(kb+4)*CTX_SV + er + mt*16 + 8];
            }
            int mc = wn*32 + lq;
            #pragma unroll
            for (int nt = 0; nt < 4; nt++){
                bfr[nt][0] = Ps[(size_t)kb*CTX_SP + mc + nt*8];
                bfr[nt][1] = Ps[(size_t)(kb+4)*CTX_SP + mc + nt*8];
            }
            #pragma unroll
            for (int mt = 0; mt < 3; mt++)
                #pragma unroll
                for (int nt = 0; nt < 4; nt++)
                    mma_tf32(acc[mt][nt], a[mt], bfr[nt]);
        }
        __syncthreads();
        if (c + 3 < 16) ldstage(c % 3, c + 3);
    }

    #pragma unroll
    for (int mt = 0; mt < 3; mt++){
        int e = wm*48 + mt*16 + lq;
        int m = m0 + wn*32 + lr*2;
        float* c0 = ctxT + ((size_t)bh*96 + e)*256;
        float* c1 = ctxT + ((size_t)bh*96 + e + 8)*256;
        #pragma unroll
        for (int nt = 0; nt < 4; nt++){
            float2 p0; p0.x = rtf32(acc[mt][nt][0]); p0.y = rtf32(acc[mt][nt][1]);
            float2 p1; p1.x = rtf32(acc[mt][nt][2]); p1.y = rtf32(acc[mt][nt][3]);
            *(float2*)(c0 + m + nt*8) = p0;
            *(float2*)(c1 + m + nt*8) = p1;
        }
    }
}

// ---------------- attn[n][h*96+e] = (pq @ ctxT^T)/den ----------------
#define ATT_STAGEF (128*36 + 96*36)
#define ATT_SMEM (3*ATT_STAGEF*4)
__global__ void __launch_bounds__(256, 1) attn_out_mma(
    const float* __restrict__ pq, const float* __restrict__ ctxT,
    const float* __restrict__ den, float* __restrict__ attn)
{
    extern __shared__ float sm[];
    int tid = threadIdx.x, lane = tid & 31, wid = tid >> 5;
    int wm = wid & 3, wn = wid >> 2;         // M(n) split 4 (32), N(e) split 2 (48)
    int n0 = blockIdx.x*128, bh = blockIdx.y;
    int b = bh >> 3, h = bh & 7;
    const float* Ab = pq + ((size_t)bh*512 + n0)*256;
    const float* Bb = ctxT + (size_t)bh*96*256;
    int lq = lane >> 2, lr = lane & 3;
    uint32_t sb = smem_u32(sm);

    auto ldstage = [&](int s, int c){
        uint32_t ab = sb + (uint32_t)s*ATT_STAGEF*4;
        #pragma unroll
        for (int i = 0; i < 4; i++){
            int p = tid + i*256; int r = p >> 3, c4 = p & 7;
            CPA16(ab + (uint32_t)(r*36 + c4*4)*4, Ab + (size_t)r*256 + c*32 + c4*4);
        }
        #pragma unroll
        for (int i = 0; i < 3; i++){
            int p = tid + i*256; int r = p >> 3, c4 = p & 7;
            CPA16(ab + (uint32_t)(128*36 + r*36 + c4*4)*4, Bb + (size_t)r*256 + c*32 + c4*4);
        }
        asm volatile("cp.async.commit_group;");
    };

    float acc[2][6][4];
    #pragma unroll
    for (int mt = 0; mt < 2; mt++)
        #pragma unroll
        for (int nt = 0; nt < 6; nt++)
            #pragma unroll
            for (int r = 0; r < 4; r++) acc[mt][nt][r] = 0.f;

    ldstage(0, 0); ldstage(1, 1); ldstage(2, 2);

    for (int c = 0; c < 8; c++){
        int pend = 7 - c;
        if (pend >= 2)      asm volatile("cp.async.wait_group 2;" ::: "memory");
        else if (pend == 1) asm volatile("cp.async.wait_group 1;" ::: "memory");
        else                asm volatile("cp.async.wait_group 0;" ::: "memory");
        __syncthreads();
        const float* As = sm + (c % 3)*ATT_STAGEF;
        const float* Bs = As + 128*36;

        #pragma unroll
        for (int k8 = 0; k8 < 4; k8++){
            int kb = k8*8 + lr;
            float a[2][4], bfr[6][2];
            int ar = wm*32 + lq;
            #pragma unroll
            for (int mt = 0; mt < 2; mt++){
                const float* p0 = As + (size_t)(ar + mt*16)*36 + kb;
                const float* p1 = As + (size_t)(ar + mt*16 + 8)*36 + kb;
                a[mt][0] = p0[0]; a[mt][1] = p1[0];
                a[mt][2] = p0[4]; a[mt][3] = p1[4];
            }
            int ec = wn*48 + lq;
            #pragma unroll
            for (int nt = 0; nt < 6; nt++){
                const float* p = Bs + (size_t)(ec + nt*8)*36 + kb;
                bfr[nt][0] = p[0]; bfr[nt][1] = p[4];
            }
            #pragma unroll
            for (int mt = 0; mt < 2; mt++)
                #pragma unroll
                for (int nt = 0; nt < 6; nt++)
                    mma_tf32(acc[mt][nt], a[mt], bfr[nt]);
        }
        __syncthreads();
        if (c + 3 < 8) ldstage(c % 3, c + 3);
    }

    #pragma unroll
    for (int mt = 0; mt < 2; mt++){
        int n = n0 + wm*32 + mt*16 + lq;
        float d0 = 1.f/den[bh*512 + n];
        float d1 = 1.f/den[bh*512 + n + 8];
        float* o0 = attn + (size_t)(b*512 + n)*768 + h*96;
        float* o1 = attn + (size_t)(b*512 + n + 8)*768 + h*96;
        int e = wn*48 + lr*2;
        #pragma unroll
        for (int nt = 0; nt < 6; nt++){
            float2 p0; p0.x = rtf32(acc[mt][nt][0]*d0); p0.y = rtf32(acc[mt][nt][1]*d0);
            float2 p1; p1.x = rtf32(acc[mt][nt][2]*d1); p1.y = rtf32(acc[mt][nt][3]*d1);
            *(float2*)(o0 + e + nt*8) = p0;
            *(float2*)(o1 + e + nt*8) = p1;
        }
    }
}

// ---------------- weight transpose / prep ----------------
__global__ void transpose_w(const float* __restrict__ src, float* __restrict__ dst,
                            int K, int N)
{
    __shared__ float t[32][33];
    int n0 = blockIdx.x*32, k0 = blockIdx.y*32;
    size_t off = (size_t)blockIdx.z * (size_t)K * N;
    src += off; dst += off;
    int tx = threadIdx.x & 31, ty = threadIdx.x >> 5;
    #pragma unroll
    for (int i = 0; i < 32; i += 8)
        t[ty+i][tx] = src[(size_t)(k0+ty+i)*N + n0+tx];
    __syncthreads();
    #pragma unroll
    for (int i = 0; i < 32; i += 8)
        dst[(size_t)(n0+ty+i)*K + k0+tx] = rtf32(t[tx][ty+i]);
}

__global__ void copy_round(const float* __restrict__ src, float* __restrict__ dst){
    int i = blockIdx.x*256 + threadIdx.x;
    dst[i] = rtf32(src[i]);
}

__global__ void im2col_kernel(const float* __restrict__ mel, float* __restrict__ dst){
    int idx = blockIdx.x*256 + threadIdx.x;
    int pg = idx >> 8, k = idx & 255;
    int b = pg >> 9, p = pg & 511;
    int oh = p >> 3, ow = p & 7;
    int i = k >> 4, j = k & 15;
    dst[idx] = rtf32(mel[(size_t)b*131072 + (size_t)(oh*16 + i)*128 + ow*16 + j]);
}

// ---------------- layernorm ----------------
__global__ void ln_kernel(const float* __restrict__ X, const float* __restrict__ sc,
                          const float* __restrict__ bb, float* __restrict__ Y)
{
    __shared__ float s1[8], s2[8];
    int row = blockIdx.x, tid = threadIdx.x;
    int lane = tid & 31, wid = tid >> 5;
    const float* xr = X + (size_t)row*DMODEL;
    float v[3]; float sum = 0.f, sq = 0.f;
    #pragma unroll
    for (int i = 0; i < 3; i++){
        v[i] = xr[tid + 256*i];
        sum += v[i]; sq += v[i]*v[i];
    }
    sum = wsum(sum); sq = wsum(sq);
    if (lane == 0){ s1[wid] = sum; s2[wid] = sq; }
    __syncthreads();
    if (tid == 0){
        float a = 0.f, b2 = 0.f;
        #pragma unroll
        for (int i = 0; i < 8; i++){ a += s1[i]; b2 += s2[i]; }
        s1[0] = a; s2[0] = b2;
    }
    __syncthreads();
    float mean = s1[0]*(1.f/768.f);
    float var  = s2[0]*(1.f/768.f) - mean*mean;
    float rstd = rsqrtf(var + 1e-5f);
    float* yr = Y + (size_t)row*DMODEL;
    #pragma unroll
    for (int i = 0; i < 3; i++){
        int d = tid + 256*i;
        yr[d] = rtf32((v[i] - mean)*rstd*sc[d] + bb[d]);
    }
}

// ---------------- FAVOR+ elementwise ----------------
__global__ void diag_kernel(const float* __restrict__ qkv, float* __restrict__ diag)
{
    if (blockIdx.x == 0 && threadIdx.x == 0) g_kmax = 0u;
    int gw = blockIdx.x*8 + (threadIdx.x >> 5);
    int lane = threadIdx.x & 31;
    int which = gw >> 15;
    int r = gw & 32767;
    int bh = r >> 9, n = r & 511;
    int b = bh >> 3, h = bh & 7;
    const float* p = qkv + (size_t)(b*512 + n)*2304 + which*768 + h*96;
    float s = 0.f;
    #pragma unroll
    for (int i = 0; i < 3; i++){ float t = p[lane + 32*i]; s += t*t; }
    s = wsum(s);
    if (lane == 0) diag[gw] = 0.05103103631f * s;
}

// pk finalize + per-feature sum, one pass
__global__ void pk_fin_sum(float* __restrict__ U, const float* __restrict__ diagk,
                           float* __restrict__ ps)
{
    int bh = blockIdx.x, m = threadIdx.x;
    float kst = dec_f(g_kmax);
    float* u = U + (size_t)bh*512*256 + m;
    const float* dg = diagk + bh*512;
    float s = 0.f;
    #pragma unroll 4
    for (int n = 0; n < 512; n++){
        float v = u[(size_t)n*256];
        float e = rtf32((expf(v - dg[n] - kst) + 1e-4f)*0.0625f);
        u[(size_t)n*256] = e;
        s += e;
    }
    ps[bh*256 + m] = s;
}

// pq finalize + denominator, one pass (warp per row)
__global__ void pq_fin_den(float* __restrict__ U, const float* __restrict__ diagq,
                           const float* __restrict__ ps, float* __restrict__ den)
{
    int gw = blockIdx.x*8 + (threadIdx.x >> 5);
    int lane = threadIdx.x & 31;
    int bh = gw >> 9;
    float* u = U + (size_t)gw*256;
    const float* s = ps + bh*256;
    float v[8]; float m = -1e30f;
    #pragma unroll
    for (int i = 0; i < 8; i++){ v[i] = u[lane + 32*i]; m = fmaxf(m, v[i]); }
    m = wmax(m);
    float d = diagq[gw];
    float a = 0.f;
    #pragma unroll
    for (int i = 0; i < 8; i++){
        float e = rtf32((expf(v[i] - d - m) + 1e-4f)*0.0625f);
        u[lane + 32*i] = e;
        a += e*s[lane + 32*i];
    }
    a = wsum(a);
    if (lane == 0) den[gw] = a;
}

// ---------------- mask head ----------------
__global__ void mask_kernel(const float* __restrict__ X, const float* __restrict__ mw,
                            const float* __restrict__ mb, float* __restrict__ out)
{
    int row = blockIdx.x;
    int tid = threadIdx.x;
    int w = tid >> 5, lane = tid & 31;
    const float* xr = X + (size_t)row*768;
    float s = 0.f;
    for (int d = lane; d < 768; d += 32) s += xr[d]*mw[d*4 + w];
    s = wsum(s);
    if (lane == 0){
        float logit = s + mb[w];
        int b = row >> 9, n = row & 511;
        out[((size_t)b*4 + w)*512 + n] = 1.f/(1.f + expf(-logit));
    }
}

// ---------------- driver ----------------
extern "C" void kernel_launch(void* const* d_in, const int* in_sizes, int n_in,
                              void* d_out, int out_size)
{
    (void)in_sizes; (void)n_in; (void)out_size;
    const float* mel     = (const float*)d_in[0];
    const float* patch_w = (const float*)d_in[1];
    const float* patch_b = (const float*)d_in[2];
    const float* pos     = (const float*)d_in[3];
    const float* proj    = (const float*)d_in[4];
    const float* ln1_s   = (const float*)d_in[5];
    const float* ln1_b   = (const float*)d_in[6];
    const float* qkv_w   = (const float*)d_in[7];
    const float* qkv_b   = (const float*)d_in[8];
    const float* ao_w    = (const float*)d_in[9];
    const float* ao_b    = (const float*)d_in[10];
    const float* ln2_s   = (const float*)d_in[11];
    const float* ln2_b   = (const float*)d_in[12];
    const float* ff1_w   = (const float*)d_in[13];
    const float* ff1_b   = (const float*)d_in[14];
    const float* ff2_w   = (const float*)d_in[15];
    const float* ff2_b   = (const float*)d_in[16];
    const float* mask_w  = (const float*)d_in[17];
    const float* mask_b  = (const float*)d_in[18];
    float* out = (float*)d_out;

    float *x, *lnb, *qkv, *ffb, *uq, *uk, *ctxb, *attn, *diag, *ps, *den, *im2, *pwT;
    float *wtq, *wtao, *wtf1, *wtf2;
    cudaGetSymbolAddress((void**)&x,    g_x);
    cudaGetSymbolAddress((void**)&lnb,  g_lnbuf);
    cudaGetSymbolAddress((void**)&qkv,  g_qkv);
    cudaGetSymbolAddress((void**)&ffb,  g_ffbuf);
    cudaGetSymbolAddress((void**)&uq,   g_uq);
    cudaGetSymbolAddress((void**)&uk,   g_uk);
    cudaGetSymbolAddress((void**)&ctxb, g_ctxb);
    cudaGetSymbolAddress((void**)&attn, g_attn);
    cudaGetSymbolAddress((void**)&diag, g_diag);
    cudaGetSymbolAddress((void**)&ps,   g_pksum);
    cudaGetSymbolAddress((void**)&den,  g_den);
    cudaGetSymbolAddress((void**)&im2,  g_im2col);
    cudaGetSymbolAddress((void**)&pwT,  g_pwT);
    cudaGetSymbolAddress((void**)&wtq,  g_wt_qkv);
    cudaGetSymbolAddress((void**)&wtao, g_wt_ao);
    cudaGetSymbolAddress((void**)&wtf1, g_wt_ff1);
    cudaGetSymbolAddress((void**)&wtf2, g_wt_ff2);

    cudaFuncSetAttribute(gemm_tc, cudaFuncAttributeMaxDynamicSharedMemorySize, GEMM_SMEM);
    cudaFuncSetAttribute(phi_u_mma, cudaFuncAttributeMaxDynamicSharedMemorySize, PHI_SMEM);
    cudaFuncSetAttribute(ctx_mma, cudaFuncAttributeMaxDynamicSharedMemorySize, CTX_SMEM);
    cudaFuncSetAttribute(attn_out_mma, cudaFuncAttributeMaxDynamicSharedMemorySize, ATT_SMEM);

    // weight prep
    copy_round<<<768, 256>>>(patch_w, pwT);
    transpose_w<<<dim3(72, 24, 6), 256>>>(qkv_w, wtq, 768, 2304);
    transpose_w<<<dim3(24, 24, 6), 256>>>(ao_w,  wtao, 768, 768);
    transpose_w<<<dim3(96, 24, 6), 256>>>(ff1_w, wtf1, 768, 3072);
    transpose_w<<<dim3(24, 96, 6), 256>>>(ff2_w, wtf2, 3072, 768);

    // patch embed
    im2col_kernel<<<4096, 256>>>(mel, im2);
    gemm_tc<<<dim3(6, 32), 128, GEMM_SMEM>>>(im2, pwT, patch_b, x, 256, 768, 3, pos);

    for (int l = 0; l < NDEPTH; l++){
        ln_kernel<<<4096, 256>>>(x, ln1_s + l*768, ln1_b + l*768, lnb);
        gemm_tc<<<dim3(18, 32), 128, GEMM_SMEM>>>(
            lnb, wtq + (size_t)l*2304*768, qkv_b + l*2304, qkv, 768, 2304, 0, 0);
        diag_kernel<<<8192, 256>>>(qkv, diag);
        phi_u_mma<<<dim3(2, 4, 64), 256, PHI_SMEM>>>(qkv, proj, uq, 0, 0);
        phi_u_mma<<<dim3(2, 4, 64), 256, PHI_SMEM>>>(qkv, proj, uk, 768, 1);
        pk_fin_sum<<<64, 256>>>(uk, diag + 32768, ps);
        pq_fin_den<<<4096, 256>>>(uq, diag, ps, den);
        ctx_mma<<<dim3(2, 64), 256, CTX_SMEM>>>(uk, qkv, ctxb);
        attn_out_mma<<<dim3(4, 64), 256, ATT_SMEM>>>(uq, ctxb, den, attn);
        gemm_tc<<<dim3(6, 32), 128, GEMM_SMEM>>>(
            attn, wtao + (size_t)l*768*768, ao_b + l*768, x, 768, 768, 2, 0);
        ln_kernel<<<4096, 256>>>(x, ln2_s + l*768, ln2_b + l*768, lnb);
        gemm_tc<<<dim3(24, 32), 128, GEMM_SMEM>>>(
            lnb, wtf1 + (size_t)l*768*3072, ff1_b + l*3072, ffb, 768, 3072, 1, 0);
        gemm_tc<<<dim3(6, 32), 128, GEMM_SMEM>>>(
            ffb, wtf2 + (size_t)l*3072*768, ff2_b + l*768, x, 3072, 768, 2, 0);
    }

    mask_kernel<<<4096, 128>>>(x, mask_w, mask_b, out);
}

// round 5
// speedup vs baseline: 3.1963x; 1.0762x over previous
#include <cuda_runtime.h>
#include <math.h>
#include <stdint.h>

#define TOK    4096   // B*N tokens
#define DMODEL 768
#define NSEQ   512
#define NHEAD  8
#define DHEAD  96
#define NFEAT  256
#define NBH    64     // B*H
#define NFF    3072
#define NDEPTH 6

// ---------------- scratch (device globals; no allocations) ----------------
__device__ float g_x[TOK*DMODEL];
__device__ float g_lnbuf[TOK*DMODEL];
__device__ float g_qkv[TOK*3*DMODEL];
__device__ float g_ffbuf[TOK*NFF];
__device__ float g_uq[NBH*NSEQ*NFEAT];
__device__ float g_uk[NBH*NSEQ*NFEAT];
__device__ float g_ctxb[NBH*DHEAD*NFEAT];   // ctxT [bh][96e][256m]
__device__ float g_attn[TOK*DMODEL];
__device__ float g_diag[2*NBH*NSEQ];
__device__ float g_pksum[NBH*NFEAT];
__device__ float g_pspart[NBH*8*NFEAT];     // partial pk sums
__device__ float g_den[NBH*NSEQ];
__device__ float g_im2col[TOK*256];
__device__ float g_pwT[DMODEL*256];
__device__ unsigned g_kmax;
// transposed (to [N][K], tf32-rounded) weights
__device__ float g_wt_qkv[NDEPTH*2304*768];
__device__ float g_wt_ao [NDEPTH*768*768];
__device__ float g_wt_ff1[NDEPTH*3072*768];
__device__ float g_wt_ff2[NDEPTH*768*3072];

// ---------------- helpers ----------------
__device__ __forceinline__ unsigned enc_f(float f){
    unsigned u = __float_as_uint(f);
    return (u & 0x80000000u) ? ~u : (u | 0x80000000u);
}
__device__ __forceinline__ float dec_f(unsigned e){
    return (e & 0x80000000u) ? __uint_as_float(e ^ 0x80000000u) : __uint_as_float(~e);
}
__device__ __forceinline__ float wsum(float v){
    #pragma unroll
    for (int o = 16; o > 0; o >>= 1) v += __shfl_xor_sync(0xffffffffu, v, o);
    return v;
}
__device__ __forceinline__ float wmax(float v){
    #pragma unroll
    for (int o = 16; o > 0; o >>= 1) v = fmaxf(v, __shfl_xor_sync(0xffffffffu, v, o));
    return v;
}
__device__ __forceinline__ float rtf32(float x){
    uint32_t o; asm("cvt.rna.tf32.f32 %0, %1;" : "=r"(o) : "f"(x));
    return __uint_as_float(o);
}
__device__ __forceinline__ uint32_t smem_u32(const void* p){
    uint32_t a;
    asm("{ .reg .u64 t; cvta.to.shared.u64 t, %1; cvt.u32.u64 %0, t; }" : "=r"(a) : "l"(p));
    return a;
}
__device__ __forceinline__ void mma_tf32(float* c, const float* a, const float* b){
    asm volatile(
        "mma.sync.aligned.m16n8k8.row.col.f32.tf32.tf32.f32 "
        "{%0,%1,%2,%3}, {%4,%5,%6,%7}, {%8,%9}, {%0,%1,%2,%3};"
        : "+f"(c[0]), "+f"(c[1]), "+f"(c[2]), "+f"(c[3])
        : "r"(__float_as_uint(a[0])), "r"(__float_as_uint(a[1])),
          "r"(__float_as_uint(a[2])), "r"(__float_as_uint(a[3])),
          "r"(__float_as_uint(b[0])), "r"(__float_as_uint(b[1])));
}
#define CPA16(saddr, gptr) \
    asm volatile("cp.async.cg.shared.global [%0], [%1], 16;" :: "r"(saddr), "l"(gptr))

// ---------------- tf32 mma.sync GEMM: C[4096,N] = A[4096,K] @ WT[N,K]^T ----------------
// 2-stage double buffer, 2 CTAs/SM for latency hiding.
#define SSTRIDE 36
#define STAGEF  (2*128*SSTRIDE)
#define GEMM_SMEM (2*STAGEF*4)
__global__ void __launch_bounds__(128, 2) gemm_tc(
    const float* __restrict__ A, const float* __restrict__ WT,
    const float* __restrict__ bias, float* __restrict__ C,
    int K, int Ncols, int ep, const float* __restrict__ aux)
{
    extern __shared__ float sm[];
    int tid = threadIdx.x, lane = tid & 31, wid = tid >> 5;
    int wm = wid & 1, wn = wid >> 1;
    int n0 = blockIdx.x*128, m0 = blockIdx.y*128;
    int NC = K >> 5;
    uint32_t sb = smem_u32(sm);

    auto ldstage = [&](int s, int c){
        uint32_t abase = sb + (uint32_t)s*STAGEF*4;
        const float* Ag = A  + (size_t)m0*K + c*32;
        const float* Bg = WT + (size_t)n0*K + c*32;
        #pragma unroll
        for (int i = 0; i < 8; i++){
            int p = tid + i*128; int r = p >> 3, c4 = p & 7;
            CPA16(abase + (uint32_t)(r*SSTRIDE + c4*4)*4, Ag + (size_t)r*K + c4*4);
        }
        #pragma unroll
        for (int i = 0; i < 8; i++){
            int p = tid + i*128; int r = p >> 3, c4 = p & 7;
            CPA16(abase + (uint32_t)(128*SSTRIDE + r*SSTRIDE + c4*4)*4, Bg + (size_t)r*K + c4*4);
        }
        asm volatile("cp.async.commit_group;");
    };

    float acc[4][8][4];
    #pragma unroll
    for (int mt = 0; mt < 4; mt++)
        #pragma unroll
        for (int nt = 0; nt < 8; nt++)
            #pragma unroll
            for (int r = 0; r < 4; r++) acc[mt][nt][r] = 0.f;

    ldstage(0, 0); ldstage(1, 1);
    int lq = lane >> 2, lr = lane & 3;

    for (int c = 0; c < NC; c++){
        if (c + 1 < NC) asm volatile("cp.async.wait_group 1;" ::: "memory");
        else            asm volatile("cp.async.wait_group 0;" ::: "memory");
        __syncthreads();

        const float* As = sm + (c & 1)*STAGEF;
        const float* Bs = As + 128*SSTRIDE;

        #pragma unroll
        for (int k8 = 0; k8 < 4; k8++){
            int kb = k8*8 + lr;
            float a[4][4], b[8][2];
            int ar = wm*64 + lq;
            #pragma unroll
            for (int mt = 0; mt < 4; mt++){
                const float* p0 = As + (size_t)(ar + mt*16)*SSTRIDE + kb;
                const float* p1 = As + (size_t)(ar + mt*16 + 8)*SSTRIDE + kb;
                a[mt][0] = p0[0]; a[mt][1] = p1[0];
                a[mt][2] = p0[4]; a[mt][3] = p1[4];
            }
            int br = wn*64 + lq;
            #pragma unroll
            for (int nt = 0; nt < 8; nt++){
                const float* p = Bs + (size_t)(br + nt*8)*SSTRIDE + kb;
                b[nt][0] = p[0]; b[nt][1] = p[4];
            }
            #pragma unroll
            for (int mt = 0; mt < 4; mt++)
                #pragma unroll
                for (int nt = 0; nt < 8; nt++)
                    mma_tf32(acc[mt][nt], a[mt], b[nt]);
        }
        __syncthreads();
        if (c + 2 < NC) ldstage(c & 1, c + 2);
    }

    int row_base = m0 + wm*64 + lq;
    int col_base = n0 + wn*64 + lr*2;
    #pragma unroll
    for (int mt = 0; mt < 4; mt++){
        #pragma unroll
        for (int h = 0; h < 2; h++){
            int row = row_base + mt*16 + h*8;
            float* crow = C + (size_t)row*Ncols;
            const float* arow = aux ? (aux + (size_t)(row & 511)*DMODEL) : (const float*)0;
            #pragma unroll
            for (int nt = 0; nt < 8; nt++){
                int col = col_base + nt*8;
                float v0 = acc[mt][nt][h*2+0] + bias[col];
                float v1 = acc[mt][nt][h*2+1] + bias[col+1];
                if (ep == 0){
                    v0 = rtf32(v0); v1 = rtf32(v1);
                } else if (ep == 1){
                    v0 = rtf32(0.5f*v0*(1.0f + erff(v0*0.70710678118654752f)));
                    v1 = rtf32(0.5f*v1*(1.0f + erff(v1*0.70710678118654752f)));
                } else if (ep == 2){
                    float2 old = *(const float2*)(crow + col);
                    v0 += old.x; v1 += old.y;
                } else if (ep == 3){
                    v0 += arow[col]; v1 += arow[col+1];
                }
                float2 o; o.x = v0; o.y = v1;
                *(float2*)(crow + col) = o;
            }
        }
    }
}

// ---------------- phi_u: per bh, U[128n x 128m] tile = cs*(X @ proj^T) ----------------
#define PHI_SMEM (3*2*128*36*4)
__global__ void __launch_bounds__(256, 1) phi_u_mma(
    const float* __restrict__ qkv, const float* __restrict__ proj,
    float* __restrict__ U, int off, int isk)
{
    extern __shared__ float sm[];
    __shared__ float red[8];
    int tid = threadIdx.x, lane = tid & 31, wid = tid >> 5;
    int wm = wid & 3, wn = wid >> 2;         // M split 4 (32), N split 2 (64)
    int m0 = blockIdx.x*128, n0 = blockIdx.y*128, bh = blockIdx.z;
    int b = bh >> 3, h = bh & 7;
    const float* Ab = qkv + (size_t)(b*512 + n0)*2304 + off + h*96;
    const float* Bb = proj + (size_t)m0*96;
    int lq = lane >> 2, lr = lane & 3;
    uint32_t sb = smem_u32(sm);

    #pragma unroll
    for (int c = 0; c < 3; c++){
        uint32_t ab = sb + (uint32_t)c*(2*128*36*4);
        #pragma unroll
        for (int i = 0; i < 4; i++){
            int p = tid + i*256; int r = p >> 3, c4 = p & 7;
            CPA16(ab + (uint32_t)(r*36 + c4*4)*4, Ab + (size_t)r*2304 + c*32 + c4*4);
        }
        #pragma unroll
        for (int i = 0; i < 4; i++){
            int p = tid + i*256; int r = p >> 3, c4 = p & 7;
            CPA16(ab + (uint32_t)(128*36 + r*36 + c4*4)*4, Bb + (size_t)r*96 + c*32 + c4*4);
        }
        asm volatile("cp.async.commit_group;");
    }

    float acc[2][8][4];
    #pragma unroll
    for (int mt = 0; mt < 2; mt++)
        #pragma unroll
        for (int nt = 0; nt < 8; nt++)
            #pragma unroll
            for (int r = 0; r < 4; r++) acc[mt][nt][r] = 0.f;

    #pragma unroll
    for (int c = 0; c < 3; c++){
        if (c == 0)      asm volatile("cp.async.wait_group 2;" ::: "memory");
        else if (c == 1) asm volatile("cp.async.wait_group 1;" ::: "memory");
        else             asm volatile("cp.async.wait_group 0;" ::: "memory");
        __syncthreads();
        const float* As = sm + c*(2*128*36);
        const float* Bs = As + 128*36;
        #pragma unroll
        for (int k8 = 0; k8 < 4; k8++){
            int kb = k8*8 + lr;
            float a[2][4], b[8][2];
            int ar = wm*32 + lq;
            #pragma unroll
            for (int mt = 0; mt < 2; mt++){
                const float* p0 = As + (size_t)(ar + mt*16)*36 + kb;
                const float* p1 = As + (size_t)(ar + mt*16 + 8)*36 + kb;
                a[mt][0] = p0[0]; a[mt][1] = p1[0];
                a[mt][2] = p0[4]; a[mt][3] = p1[4];
            }
            int bc = wn*64 + lq;
            #pragma unroll
            for (int nt = 0; nt < 8; nt++){
                const float* p = Bs + (size_t)(bc + nt*8)*36 + kb;
                b[nt][0] = p[0]; b[nt][1] = p[4];
            }
            #pragma unroll
            for (int mt = 0; mt < 2; mt++)
                #pragma unroll
                for (int nt = 0; nt < 8; nt++)
                    mma_tf32(acc[mt][nt], a[mt], b[nt]);
        }
    }

    const float cs = 0.31947155f;   // 96^{-1/4}
    float tmax = -1e30f;
    #pragma unroll
    for (int mt = 0; mt < 2; mt++){
        int n = n0 + wm*32 + mt*16 + lq;
        int m = m0 + wn*64 + lr*2;
        float* u0 = U + ((size_t)bh*512 + n)*256;
        float* u1 = U + ((size_t)bh*512 + n + 8)*256;
        #pragma unroll
        for (int nt = 0; nt < 8; nt++){
            float v0 = acc[mt][nt][0]*cs, v1 = acc[mt][nt][1]*cs;
            float v2 = acc[mt][nt][2]*cs, v3 = acc[mt][nt][3]*cs;
            float2 p0; p0.x = v0; p0.y = v1;
            float2 p1; p1.x = v2; p1.y = v3;
            *(float2*)(u0 + m + nt*8) = p0;
            *(float2*)(u1 + m + nt*8) = p1;
            tmax = fmaxf(tmax, fmaxf(fmaxf(v0, v1), fmaxf(v2, v3)));
        }
    }
    if (isk){
        tmax = wmax(tmax);
        if (lane == 0) red[wid] = tmax;
        __syncthreads();
        if (tid == 0){
            float m = red[0];
            #pragma unroll
            for (int i = 1; i < 8; i++) m = fmaxf(m, red[i]);
            atomicMax(&g_kmax, enc_f(m));
        }
    }
}

// ---------------- ctxT[bh][96e][256m] = sum_n V[n][e]*pk[n][m] ----------------
#define CTX_SV 104
#define CTX_SP 136
#define CTX_STAGEF (32*CTX_SV + 32*CTX_SP)
#define CTX_SMEM (3*CTX_STAGEF*4)
__global__ void __launch_bounds__(256, 1) ctx_mma(
    const float* __restrict__ pk, const float* __restrict__ qkv,
    float* __restrict__ ctxT)
{
    extern __shared__ float sm[];
    int tid = threadIdx.x, lane = tid & 31, wid = tid >> 5;
    int wm = wid & 1, wn = wid >> 1;         // M(e) split 2 (48), N(m) split 4 (32)
    int m0 = blockIdx.x*128, bh = blockIdx.y;
    int b = bh >> 3, h = bh & 7;
    const float* Vb = qkv + (size_t)(b*512)*2304 + 1536 + h*96;
    const float* Pb = pk + (size_t)(bh*512)*256 + m0;
    int lq = lane >> 2, lr = lane & 3;
    uint32_t sb = smem_u32(sm);

    auto ldstage = [&](int s, int c){
        uint32_t ab = sb + (uint32_t)s*CTX_STAGEF*4;
        #pragma unroll
        for (int i = 0; i < 3; i++){
            int p = tid + i*256; int r = p/24, cc = p - r*24;
            CPA16(ab + (uint32_t)(r*CTX_SV + cc*4)*4, Vb + (size_t)(c*32 + r)*2304 + cc*4);
        }
        #pragma unroll
        for (int i = 0; i < 4; i++){
            int p = tid + i*256; int r = p >> 5, cc = p & 31;
            CPA16(ab + (uint32_t)(32*CTX_SV + r*CTX_SP + cc*4)*4,
                  Pb + (size_t)(c*32 + r)*256 + cc*4);
        }
        asm volatile("cp.async.commit_group;");
    };

    float acc[3][4][4];
    #pragma unroll
    for (int mt = 0; mt < 3; mt++)
        #pragma unroll
        for (int nt = 0; nt < 4; nt++)
            #pragma unroll
            for (int r = 0; r < 4; r++) acc[mt][nt][r] = 0.f;

    ldstage(0, 0); ldstage(1, 1); ldstage(2, 2);

    for (int c = 0; c < 16; c++){
        int pend = 15 - c;
        if (pend >= 2)      asm volatile("cp.async.wait_group 2;" ::: "memory");
        else if (pend == 1) asm volatile("cp.async.wait_group 1;" ::: "memory");
        else                asm volatile("cp.async.wait_group 0;" ::: "memory");
        __syncthreads();
        const float* Vs = sm + (c % 3)*CTX_STAGEF;
        const float* Ps = Vs + 32*CTX_SV;

        #pragma unroll
        for (int k8 = 0; k8 < 4; k8++){
            int kb = k8*8 + lr;
            float a[3][4], bfr[4][2];
            int er = wm*48 + lq;
            #pragma unroll
            for (int mt = 0; mt < 3; mt++){
                a[mt][0] = Vs[(size_t)kb*CTX_SV + er + mt*16];
                a[mt][1] = Vs[(size_t)kb*CTX_SV + er + mt*16 + 8];
                a[mt][2] = Vs[(size_t)(kb+4)*CTX_SV + er + mt*16];
                a[mt][3] = Vs[(size_t)(kb+4)*CTX_SV + er + mt*16 + 8];
            }
            int mc = wn*32 + lq;
            #pragma unroll
            for (int nt = 0; nt < 4; nt++){
                bfr[nt][0] = Ps[(size_t)kb*CTX_SP + mc + nt*8];
                bfr[nt][1] = Ps[(size_t)(kb+4)*CTX_SP + mc + nt*8];
            }
            #pragma unroll
            for (int mt = 0; mt < 3; mt++)
                #pragma unroll
                for (int nt = 0; nt < 4; nt++)
                    mma_tf32(acc[mt][nt], a[mt], bfr[nt]);
        }
        __syncthreads();
        if (c + 3 < 16) ldstage(c % 3, c + 3);
    }

    #pragma unroll
    for (int mt = 0; mt < 3; mt++){
        int e = wm*48 + mt*16 + lq;
        int m = m0 + wn*32 + lr*2;
        float* c0 = ctxT + ((size_t)bh*96 + e)*256;
        float* c1 = ctxT + ((size_t)bh*96 + e + 8)*256;
        #pragma unroll
        for (int nt = 0; nt < 4; nt++){
            float2 p0; p0.x = rtf32(acc[mt][nt][0]); p0.y = rtf32(acc[mt][nt][1]);
            float2 p1; p1.x = rtf32(acc[mt][nt][2]); p1.y = rtf32(acc[mt][nt][3]);
            *(float2*)(c0 + m + nt*8) = p0;
            *(float2*)(c1 + m + nt*8) = p1;
        }
    }
}

// ---------------- attn[n][h*96+e] = (pq @ ctxT^T)/den ----------------
#define ATT_STAGEF (128*36 + 96*36)
#define ATT_SMEM (3*ATT_STAGEF*4)
__global__ void __launch_bounds__(256, 1) attn_out_mma(
    const float* __restrict__ pq, const float* __restrict__ ctxT,
    const float* __restrict__ den, float* __restrict__ attn)
{
    extern __shared__ float sm[];
    int tid = threadIdx.x, lane = tid & 31, wid = tid >> 5;
    int wm = wid & 3, wn = wid >> 2;         // M(n) split 4 (32), N(e) split 2 (48)
    int n0 = blockIdx.x*128, bh = blockIdx.y;
    int b = bh >> 3, h = bh & 7;
    const float* Ab = pq + ((size_t)bh*512 + n0)*256;
    const float* Bb = ctxT + (size_t)bh*96*256;
    int lq = lane >> 2, lr = lane & 3;
    uint32_t sb = smem_u32(sm);

    auto ldstage = [&](int s, int c){
        uint32_t ab = sb + (uint32_t)s*ATT_STAGEF*4;
        #pragma unroll
        for (int i = 0; i < 4; i++){
            int p = tid + i*256; int r = p >> 3, c4 = p & 7;
            CPA16(ab + (uint32_t)(r*36 + c4*4)*4, Ab + (size_t)r*256 + c*32 + c4*4);
        }
        #pragma unroll
        for (int i = 0; i < 3; i++){
            int p = tid + i*256; int r = p >> 3, c4 = p & 7;
            CPA16(ab + (uint32_t)(128*36 + r*36 + c4*4)*4, Bb + (size_t)r*256 + c*32 + c4*4);
        }
        asm volatile("cp.async.commit_group;");
    };

    float acc[2][6][4];
    #pragma unroll
    for (int mt = 0; mt < 2; mt++)
        #pragma unroll
        for (int nt = 0; nt < 6; nt++)
            #pragma unroll
            for (int r = 0; r < 4; r++) acc[mt][nt][r] = 0.f;

    ldstage(0, 0); ldstage(1, 1); ldstage(2, 2);

    for (int c = 0; c < 8; c++){
        int pend = 7 - c;
        if (pend >= 2)      asm volatile("cp.async.wait_group 2;" ::: "memory");
        else if (pend == 1) asm volatile("cp.async.wait_group 1;" ::: "memory");
        else                asm volatile("cp.async.wait_group 0;" ::: "memory");
        __syncthreads();
        const float* As = sm + (c % 3)*ATT_STAGEF;
        const float* Bs = As + 128*36;

        #pragma unroll
        for (int k8 = 0; k8 < 4; k8++){
            int kb = k8*8 + lr;
            float a[2][4], bfr[6][2];
            int ar = wm*32 + lq;
            #pragma unroll
            for (int mt = 0; mt < 2; mt++){
                const float* p0 = As + (size_t)(ar + mt*16)*36 + kb;
                const float* p1 = As + (size_t)(ar + mt*16 + 8)*36 + kb;
                a[mt][0] = p0[0]; a[mt][1] = p1[0];
                a[mt][2] = p0[4]; a[mt][3] = p1[4];
            }
            int ec = wn*48 + lq;
            #pragma unroll
            for (int nt = 0; nt < 6; nt++){
                const float* p = Bs + (size_t)(ec + nt*8)*36 + kb;
                bfr[nt][0] = p[0]; bfr[nt][1] = p[4];
            }
            #pragma unroll
            for (int mt = 0; mt < 2; mt++)
                #pragma unroll
                for (int nt = 0; nt < 6; nt++)
                    mma_tf32(acc[mt][nt], a[mt], bfr[nt]);
        }
        __syncthreads();
        if (c + 3 < 8) ldstage(c % 3, c + 3);
    }

    #pragma unroll
    for (int mt = 0; mt < 2; mt++){
        int n = n0 + wm*32 + mt*16 + lq;
        float d0 = 1.f/den[bh*512 + n];
        float d1 = 1.f/den[bh*512 + n + 8];
        float* o0 = attn + (size_t)(b*512 + n)*768 + h*96;
        float* o1 = attn + (size_t)(b*512 + n + 8)*768 + h*96;
        int e = wn*48 + lr*2;
        #pragma unroll
        for (int nt = 0; nt < 6; nt++){
            float2 p0; p0.x = rtf32(acc[mt][nt][0]*d0); p0.y = rtf32(acc[mt][nt][1]*d0);
            float2 p1; p1.x = rtf32(acc[mt][nt][2]*d1); p1.y = rtf32(acc[mt][nt][3]*d1);
            *(float2*)(o0 + e + nt*8) = p0;
            *(float2*)(o1 + e + nt*8) = p1;
        }
    }
}

// ---------------- weight transpose / prep ----------------
__global__ void transpose_w(const float* __restrict__ src, float* __restrict__ dst,
                            int K, int N)
{
    __shared__ float t[32][33];
    int n0 = blockIdx.x*32, k0 = blockIdx.y*32;
    size_t off = (size_t)blockIdx.z * (size_t)K * N;
    src += off; dst += off;
    int tx = threadIdx.x & 31, ty = threadIdx.x >> 5;
    #pragma unroll
    for (int i = 0; i < 32; i += 8)
        t[ty+i][tx] = src[(size_t)(k0+ty+i)*N + n0+tx];
    __syncthreads();
    #pragma unroll
    for (int i = 0; i < 32; i += 8)
        dst[(size_t)(n0+ty+i)*K + k0+tx] = rtf32(t[tx][ty+i]);
}

__global__ void copy_round(const float* __restrict__ src, float* __restrict__ dst){
    int i = blockIdx.x*256 + threadIdx.x;
    dst[i] = rtf32(src[i]);
}

__global__ void im2col_kernel(const float* __restrict__ mel, float* __restrict__ dst){
    int idx = blockIdx.x*256 + threadIdx.x;
    int pg = idx >> 8, k = idx & 255;
    int b = pg >> 9, p = pg & 511;
    int oh = p >> 3, ow = p & 7;
    int i = k >> 4, j = k & 15;
    dst[idx] = rtf32(mel[(size_t)b*131072 + (size_t)(oh*16 + i)*128 + ow*16 + j]);
}

// ---------------- layernorm ----------------
__global__ void ln_kernel(const float* __restrict__ X, const float* __restrict__ sc,
                          const float* __restrict__ bb, float* __restrict__ Y)
{
    __shared__ float s1[8], s2[8];
    int row = blockIdx.x, tid = threadIdx.x;
    int lane = tid & 31, wid = tid >> 5;
    const float* xr = X + (size_t)row*DMODEL;
    float v[3]; float sum = 0.f, sq = 0.f;
    #pragma unroll
    for (int i = 0; i < 3; i++){
        v[i] = xr[tid + 256*i];
        sum += v[i]; sq += v[i]*v[i];
    }
    sum = wsum(sum); sq = wsum(sq);
    if (lane == 0){ s1[wid] = sum; s2[wid] = sq; }
    __syncthreads();
    if (tid == 0){
        float a = 0.f, b2 = 0.f;
        #pragma unroll
        for (int i = 0; i < 8; i++){ a += s1[i]; b2 += s2[i]; }
        s1[0] = a; s2[0] = b2;
    }
    __syncthreads();
    float mean = s1[0]*(1.f/768.f);
    float var  = s2[0]*(1.f/768.f) - mean*mean;
    float rstd = rsqrtf(var + 1e-5f);
    float* yr = Y + (size_t)row*DMODEL;
    #pragma unroll
    for (int i = 0; i < 3; i++){
        int d = tid + 256*i;
        yr[d] = rtf32((v[i] - mean)*rstd*sc[d] + bb[d]);
    }
}

// ---------------- FAVOR+ elementwise ----------------
__global__ void diag_kernel(const float* __restrict__ qkv, float* __restrict__ diag)
{
    if (blockIdx.x == 0 && threadIdx.x == 0) g_kmax = 0u;
    int gw = blockIdx.x*8 + (threadIdx.x >> 5);
    int lane = threadIdx.x & 31;
    int which = gw >> 15;
    int r = gw & 32767;
    int bh = r >> 9, n = r & 511;
    int b = bh >> 3, h = bh & 7;
    const float* p = qkv + (size_t)(b*512 + n)*2304 + which*768 + h*96;
    float s = 0.f;
    #pragma unroll
    for (int i = 0; i < 3; i++){ float t = p[lane + 32*i]; s += t*t; }
    s = wsum(s);
    if (lane == 0) diag[gw] = 0.05103103631f * s;
}

// pk finalize + partial per-feature sums: grid (bh, chunk of 64 rows)
__global__ void pk_fin_part(float* __restrict__ U, const float* __restrict__ diagk,
                            float* __restrict__ pspart)
{
    int bh = blockIdx.x, ch = blockIdx.y, m = threadIdx.x;
    float kst = dec_f(g_kmax);
    float* u = U + ((size_t)bh*512 + ch*64)*256 + m;
    const float* dg = diagk + bh*512 + ch*64;
    float s = 0.f;
    #pragma unroll 4
    for (int n = 0; n < 64; n++){
        float v = u[(size_t)n*256];
        float e = rtf32((expf(v - dg[n] - kst) + 1e-4f)*0.0625f);
        u[(size_t)n*256] = e;
        s += e;
    }
    pspart[((size_t)bh*8 + ch)*256 + m] = s;
}

// reduce 8 partials -> pksum (deterministic fixed order)
__global__ void ps_reduce(const float* __restrict__ pspart, float* __restrict__ ps)
{
    int bh = blockIdx.x, m = threadIdx.x;
    const float* p = pspart + (size_t)bh*8*256 + m;
    float s = 0.f;
    #pragma unroll
    for (int c = 0; c < 8; c++) s += p[c*256];
    ps[bh*256 + m] = s;
}

// pq finalize + denominator, one pass (warp per row)
__global__ void pq_fin_den(float* __restrict__ U, const float* __restrict__ diagq,
                           const float* __restrict__ ps, float* __restrict__ den)
{
    int gw = blockIdx.x*8 + (threadIdx.x >> 5);
    int lane = threadIdx.x & 31;
    int bh = gw >> 9;
    float* u = U + (size_t)gw*256;
    const float* s = ps + bh*256;
    float v[8]; float m = -1e30f;
    #pragma unroll
    for (int i = 0; i < 8; i++){ v[i] = u[lane + 32*i]; m = fmaxf(m, v[i]); }
    m = wmax(m);
    float d = diagq[gw];
    float a = 0.f;
    #pragma unroll
    for (int i = 0; i < 8; i++){
        float e = rtf32((expf(v[i] - d - m) + 1e-4f)*0.0625f);
        u[lane + 32*i] = e;
        a += e*s[lane + 32*i];
    }
    a = wsum(a);
    if (lane == 0) den[gw] = a;
}

// ---------------- mask head ----------------
__global__ void mask_kernel(const float* __restrict__ X, const float* __restrict__ mw,
                            const float* __restrict__ mb, float* __restrict__ out)
{
    int row = blockIdx.x;
    int tid = threadIdx.x;
    int w = tid >> 5, lane = tid & 31;
    const float* xr = X + (size_t)row*768;
    float s = 0.f;
    for (int d = lane; d < 768; d += 32) s += xr[d]*mw[d*4 + w];
    s = wsum(s);
    if (lane == 0){
        float logit = s + mb[w];
        int b = row >> 9, n = row & 511;
        out[((size_t)b*4 + w)*512 + n] = 1.f/(1.f + expf(-logit));
    }
}

// ---------------- driver ----------------
extern "C" void kernel_launch(void* const* d_in, const int* in_sizes, int n_in,
                              void* d_out, int out_size)
{
    (void)in_sizes; (void)n_in; (void)out_size;
    const float* mel     = (const float*)d_in[0];
    const float* patch_w = (const float*)d_in[1];
    const float* patch_b = (const float*)d_in[2];
    const float* pos     = (const float*)d_in[3];
    const float* proj    = (const float*)d_in[4];
    const float* ln1_s   = (const float*)d_in[5];
    const float* ln1_b   = (const float*)d_in[6];
    const float* qkv_w   = (const float*)d_in[7];
    const float* qkv_b   = (const float*)d_in[8];
    const float* ao_w    = (const float*)d_in[9];
    const float* ao_b    = (const float*)d_in[10];
    const float* ln2_s   = (const float*)d_in[11];
    const float* ln2_b   = (const float*)d_in[12];
    const float* ff1_w   = (const float*)d_in[13];
    const float* ff1_b   = (const float*)d_in[14];
    const float* ff2_w   = (const float*)d_in[15];
    const float* ff2_b   = (const float*)d_in[16];
    const float* mask_w  = (const float*)d_in[17];
    const float* mask_b  = (const float*)d_in[18];
    float* out = (float*)d_out;

    float *x, *lnb, *qkv, *ffb, *uq, *uk, *ctxb, *attn, *diag, *ps, *psp, *den, *im2, *pwT;
    float *wtq, *wtao, *wtf1, *wtf2;
    cudaGetSymbolAddress((void**)&x,    g_x);
    cudaGetSymbolAddress((void**)&lnb,  g_lnbuf);
    cudaGetSymbolAddress((void**)&qkv,  g_qkv);
    cudaGetSymbolAddress((void**)&ffb,  g_ffbuf);
    cudaGetSymbolAddress((void**)&uq,   g_uq);
    cudaGetSymbolAddress((void**)&uk,   g_uk);
    cudaGetSymbolAddress((void**)&ctxb, g_ctxb);
    cudaGetSymbolAddress((void**)&attn, g_attn);
    cudaGetSymbolAddress((void**)&diag, g_diag);
    cudaGetSymbolAddress((void**)&ps,   g_pksum);
    cudaGetSymbolAddress((void**)&psp,  g_pspart);
    cudaGetSymbolAddress((void**)&den,  g_den);
    cudaGetSymbolAddress((void**)&im2,  g_im2col);
    cudaGetSymbolAddress((void**)&pwT,  g_pwT);
    cudaGetSymbolAddress((void**)&wtq,  g_wt_qkv);
    cudaGetSymbolAddress((void**)&wtao, g_wt_ao);
    cudaGetSymbolAddress((void**)&wtf1, g_wt_ff1);
    cudaGetSymbolAddress((void**)&wtf2, g_wt_ff2);

    cudaFuncSetAttribute(gemm_tc, cudaFuncAttributeMaxDynamicSharedMemorySize, GEMM_SMEM);
    cudaFuncSetAttribute(phi_u_mma, cudaFuncAttributeMaxDynamicSharedMemorySize, PHI_SMEM);
    cudaFuncSetAttribute(ctx_mma, cudaFuncAttributeMaxDynamicSharedMemorySize, CTX_SMEM);
    cudaFuncSetAttribute(attn_out_mma, cudaFuncAttributeMaxDynamicSharedMemorySize, ATT_SMEM);

    // weight prep
    copy_round<<<768, 256>>>(patch_w, pwT);
    transpose_w<<<dim3(72, 24, 6), 256>>>(qkv_w, wtq, 768, 2304);
    transpose_w<<<dim3(24, 24, 6), 256>>>(ao_w,  wtao, 768, 768);
    transpose_w<<<dim3(96, 24, 6), 256>>>(ff1_w, wtf1, 768, 3072);
    transpose_w<<<dim3(24, 96, 6), 256>>>(ff2_w, wtf2, 3072, 768);

    // patch embed
    im2col_kernel<<<4096, 256>>>(mel, im2);
    gemm_tc<<<dim3(6, 32), 128, GEMM_SMEM>>>(im2, pwT, patch_b, x, 256, 768, 3, pos);

    for (int l = 0; l < NDEPTH; l++){
        ln_kernel<<<4096, 256>>>(x, ln1_s + l*768, ln1_b + l*768, lnb);
        gemm_tc<<<dim3(18, 32), 128, GEMM_SMEM>>>(
            lnb, wtq + (size_t)l*2304*768, qkv_b + l*2304, qkv, 768, 2304, 0, 0);
        diag_kernel<<<8192, 256>>>(qkv, diag);
        phi_u_mma<<<dim3(2, 4, 64), 256, PHI_SMEM>>>(qkv, proj, uq, 0, 0);
        phi_u_mma<<<dim3(2, 4, 64), 256, PHI_SMEM>>>(qkv, proj, uk, 768, 1);
        pk_fin_part<<<dim3(64, 8), 256>>>(uk, diag + 32768, psp);
        ps_reduce<<<64, 256>>>(psp, ps);
        pq_fin_den<<<4096, 256>>>(uq, diag, ps, den);
        ctx_mma<<<dim3(2, 64), 256, CTX_SMEM>>>(uk, qkv, ctxb);
        attn_out_mma<<<dim3(4, 64), 256, ATT_SMEM>>>(uq, ctxb, den, attn);
        gemm_tc<<<dim3(6, 32), 128, GEMM_SMEM>>>(
            attn, wtao + (size_t)l*768*768, ao_b + l*768, x, 768, 768, 2, 0);
        ln_kernel<<<4096, 256>>>(x, ln2_s + l*768, ln2_b + l*768, lnb);
        gemm_tc<<<dim3(24, 32), 128, GEMM_SMEM>>>(
            lnb, wtf1 + (size_t)l*768*3072, ff1_b + l*3072, ffb, 768, 3072, 1, 0);
        gemm_tc<<<dim3(6, 32), 128, GEMM_SMEM>>>(
            ffb, wtf2 + (size_t)l*3072*768, ff2_b + l*768, x, 3072, 768, 2, 0);
    }

    mask_kernel<<<4096, 128>>>(x, mask_w, mask_b, out);
}

// round 6
// speedup vs baseline: 3.2537x; 1.0180x over previous
#include <cuda_runtime.h>
#include <math.h>
#include <stdint.h>

#define TOK    4096
#define DMODEL 768
#define NSEQ   512
#define NHEAD  8
#define DHEAD  96
#define NFEAT  256
#define NBH    64
#define NFF    3072
#define NDEPTH 6

// ---------------- scratch ----------------
__device__ float g_x[TOK*DMODEL];
__device__ float g_lnbuf[TOK*DMODEL];
__device__ float g_qkv[TOK*3*DMODEL];
__device__ float g_ffbuf[TOK*NFF];
__device__ float g_uq[NBH*NSEQ*NFEAT];
__device__ float g_uk[NBH*NSEQ*NFEAT];
__device__ float g_ctxb[NBH*DHEAD*NFEAT];   // ctxT [bh][96e][256m]
__device__ float g_attn[TOK*DMODEL];
__device__ float g_diag[2*NBH*NSEQ];
__device__ float g_pksum[NBH*NFEAT];
__device__ float g_pspart[NBH*8*NFEAT];
__device__ float g_den[NBH*NSEQ];
__device__ float g_im2col[TOK*256];
__device__ float g_pwT[DMODEL*256];
__device__ unsigned g_kmax;
__device__ float g_wt_qkv[NDEPTH*2304*768];
__device__ float g_wt_ao [NDEPTH*768*768];
__device__ float g_wt_ff1[NDEPTH*3072*768];
__device__ float g_wt_ff2[NDEPTH*768*3072];

// ---------------- helpers ----------------
__device__ __forceinline__ unsigned enc_f(float f){
    unsigned u = __float_as_uint(f);
    return (u & 0x80000000u) ? ~u : (u | 0x80000000u);
}
__device__ __forceinline__ float dec_f(unsigned e){
    return (e & 0x80000000u) ? __uint_as_float(e ^ 0x80000000u) : __uint_as_float(~e);
}
__device__ __forceinline__ float wsum(float v){
    #pragma unroll
    for (int o = 16; o > 0; o >>= 1) v += __shfl_xor_sync(0xffffffffu, v, o);
    return v;
}
__device__ __forceinline__ float wmax(float v){
    #pragma unroll
    for (int o = 16; o > 0; o >>= 1) v = fmaxf(v, __shfl_xor_sync(0xffffffffu, v, o));
    return v;
}
__device__ __forceinline__ float rtf32(float x){
    uint32_t o; asm("cvt.rna.tf32.f32 %0, %1;" : "=r"(o) : "f"(x));
    return __uint_as_float(o);
}
__device__ __forceinline__ uint32_t smem_u32(const void* p){
    uint32_t a;
    asm("{ .reg .u64 t; cvta.to.shared.u64 t, %1; cvt.u32.u64 %0, t; }" : "=r"(a) : "l"(p));
    return a;
}
__device__ __forceinline__ void mma_tf32(float* c, const float* a, const float* b){
    asm volatile(
        "mma.sync.aligned.m16n8k8.row.col.f32.tf32.tf32.f32 "
        "{%0,%1,%2,%3}, {%4,%5,%6,%7}, {%8,%9}, {%0,%1,%2,%3};"
        : "+f"(c[0]), "+f"(c[1]), "+f"(c[2]), "+f"(c[3])
        : "r"(__float_as_uint(a[0])), "r"(__float_as_uint(a[1])),
          "r"(__float_as_uint(a[2])), "r"(__float_as_uint(a[3])),
          "r"(__float_as_uint(b[0])), "r"(__float_as_uint(b[1])));
}
#define CPA16(saddr, gptr) \
    asm volatile("cp.async.cg.shared.global [%0], [%1], 16;" :: "r"(saddr), "l"(gptr))

// ---------------- tf32 mma.sync GEMM: 3-stage, 2 CTAs/SM ----------------
#define SSTRIDE 36
#define STAGEF  (2*128*SSTRIDE)
#define GEMM_SMEM (3*STAGEF*4)
__global__ void __launch_bounds__(128, 2) gemm_tc(
    const float* __restrict__ A, const float* __restrict__ WT,
    const float* __restrict__ bias, float* __restrict__ C,
    int K, int Ncols, int ep, const float* __restrict__ aux)
{
    extern __shared__ float sm[];
    int tid = threadIdx.x, lane = tid & 31, wid = tid >> 5;
    int wm = wid & 1, wn = wid >> 1;
    int n0 = blockIdx.x*128, m0 = blockIdx.y*128;
    int NC = K >> 5;
    uint32_t sb = smem_u32(sm);

    auto ldstage = [&](int s, int c){
        uint32_t abase = sb + (uint32_t)s*STAGEF*4;
        const float* Ag = A  + (size_t)m0*K + c*32;
        const float* Bg = WT + (size_t)n0*K + c*32;
        #pragma unroll
        for (int i = 0; i < 8; i++){
            int p = tid + i*128; int r = p >> 3, c4 = p & 7;
            CPA16(abase + (uint32_t)(r*SSTRIDE + c4*4)*4, Ag + (size_t)r*K + c4*4);
        }
        #pragma unroll
        for (int i = 0; i < 8; i++){
            int p = tid + i*128; int r = p >> 3, c4 = p & 7;
            CPA16(abase + (uint32_t)(128*SSTRIDE + r*SSTRIDE + c4*4)*4, Bg + (size_t)r*K + c4*4);
        }
        asm volatile("cp.async.commit_group;");
    };

    float acc[4][8][4];
    #pragma unroll
    for (int mt = 0; mt < 4; mt++)
        #pragma unroll
        for (int nt = 0; nt < 8; nt++)
            #pragma unroll
            for (int r = 0; r < 4; r++) acc[mt][nt][r] = 0.f;

    ldstage(0, 0); ldstage(1, 1); ldstage(2, 2);
    int lq = lane >> 2, lr = lane & 3;

    for (int c = 0; c < NC; c++){
        int pend = NC - 1 - c;
        if (pend >= 2)      asm volatile("cp.async.wait_group 2;" ::: "memory");
        else if (pend == 1) asm volatile("cp.async.wait_group 1;" ::: "memory");
        else                asm volatile("cp.async.wait_group 0;" ::: "memory");
        __syncthreads();

        const float* As = sm + (c % 3)*STAGEF;
        const float* Bs = As + 128*SSTRIDE;

        #pragma unroll
        for (int k8 = 0; k8 < 4; k8++){
            int kb = k8*8 + lr;
            float a[4][4], b[8][2];
            int ar = wm*64 + lq;
            #pragma unroll
            for (int mt = 0; mt < 4; mt++){
                const float* p0 = As + (size_t)(ar + mt*16)*SSTRIDE + kb;
                const float* p1 = As + (size_t)(ar + mt*16 + 8)*SSTRIDE + kb;
                a[mt][0] = p0[0]; a[mt][1] = p1[0];
                a[mt][2] = p0[4]; a[mt][3] = p1[4];
            }
            int br = wn*64 + lq;
            #pragma unroll
            for (int nt = 0; nt < 8; nt++){
                const float* p = Bs + (size_t)(br + nt*8)*SSTRIDE + kb;
                b[nt][0] = p[0]; b[nt][1] = p[4];
            }
            #pragma unroll
            for (int mt = 0; mt < 4; mt++)
                #pragma unroll
                for (int nt = 0; nt < 8; nt++)
                    mma_tf32(acc[mt][nt], a[mt], b[nt]);
        }
        __syncthreads();
        if (c + 3 < NC) ldstage(c % 3, c + 3);
    }

    int row_base = m0 + wm*64 + lq;
    int col_base = n0 + wn*64 + lr*2;
    #pragma unroll
    for (int mt = 0; mt < 4; mt++){
        #pragma unroll
        for (int h = 0; h < 2; h++){
            int row = row_base + mt*16 + h*8;
            float* crow = C + (size_t)row*Ncols;
            const float* arow = aux ? (aux + (size_t)(row & 511)*DMODEL) : (const float*)0;
            #pragma unroll
            for (int nt = 0; nt < 8; nt++){
                int col = col_base + nt*8;
                float v0 = acc[mt][nt][h*2+0] + bias[col];
                float v1 = acc[mt][nt][h*2+1] + bias[col+1];
                if (ep == 0){
                    v0 = rtf32(v0); v1 = rtf32(v1);
                } else if (ep == 1){
                    v0 = rtf32(0.5f*v0*(1.0f + erff(v0*0.70710678118654752f)));
                    v1 = rtf32(0.5f*v1*(1.0f + erff(v1*0.70710678118654752f)));
                } else if (ep == 2){
                    float2 old = *(const float2*)(crow + col);
                    v0 += old.x; v1 += old.y;
                } else if (ep == 3){
                    v0 += arow[col]; v1 += arow[col+1];
                }
                float2 o; o.x = v0; o.y = v1;
                *(float2*)(crow + col) = o;
            }
        }
    }
}

// ---------------- phi_u (q+k combined) + fused diag ----------------
#define PHI_SMEM (3*2*128*36*4)
__global__ void __launch_bounds__(256, 2) phi_u_mma(
    const float* __restrict__ qkv, const float* __restrict__ proj,
    float* __restrict__ uq, float* __restrict__ uk, float* __restrict__ diag)
{
    extern __shared__ float sm[];
    __shared__ float red[8];
    int tid = threadIdx.x, lane = tid & 31, wid = tid >> 5;
    int wm = wid & 3, wn = wid >> 2;         // M split 4 (32), N split 2 (64)
    int m0 = blockIdx.x*128, n0 = blockIdx.y*128;
    int zz = blockIdx.z;
    int bh = zz & 63, isk = zz >> 6;
    int b = bh >> 3, h = bh & 7;
    float* U = isk ? uk : uq;
    const float* Ab = qkv + (size_t)(b*512 + n0)*2304 + isk*768 + h*96;
    const float* Bb = proj + (size_t)m0*96;
    int lq = lane >> 2, lr = lane & 3;
    uint32_t sb = smem_u32(sm);

    #pragma unroll
    for (int c = 0; c < 3; c++){
        uint32_t ab = sb + (uint32_t)c*(2*128*36*4);
        #pragma unroll
        for (int i = 0; i < 4; i++){
            int p = tid + i*256; int r = p >> 3, c4 = p & 7;
            CPA16(ab + (uint32_t)(r*36 + c4*4)*4, Ab + (size_t)r*2304 + c*32 + c4*4);
        }
        #pragma unroll
        for (int i = 0; i < 4; i++){
            int p = tid + i*256; int r = p >> 3, c4 = p & 7;
            CPA16(ab + (uint32_t)(128*36 + r*36 + c4*4)*4, Bb + (size_t)r*96 + c*32 + c4*4);
        }
        asm volatile("cp.async.commit_group;");
    }

    float acc[2][8][4];
    #pragma unroll
    for (int mt = 0; mt < 2; mt++)
        #pragma unroll
        for (int nt = 0; nt < 8; nt++)
            #pragma unroll
            for (int r = 0; r < 4; r++) acc[mt][nt][r] = 0.f;

    #pragma unroll
    for (int c = 0; c < 3; c++){
        if (c == 0)      asm volatile("cp.async.wait_group 2;" ::: "memory");
        else if (c == 1) asm volatile("cp.async.wait_group 1;" ::: "memory");
        else             asm volatile("cp.async.wait_group 0;" ::: "memory");
        __syncthreads();
        const float* As = sm + c*(2*128*36);
        const float* Bs = As + 128*36;
        #pragma unroll
        for (int k8 = 0; k8 < 4; k8++){
            int kb = k8*8 + lr;
            float a[2][4], b[8][2];
            int ar = wm*32 + lq;
            #pragma unroll
            for (int mt = 0; mt < 2; mt++){
                const float* p0 = As + (size_t)(ar + mt*16)*36 + kb;
                const float* p1 = As + (size_t)(ar + mt*16 + 8)*36 + kb;
                a[mt][0] = p0[0]; a[mt][1] = p1[0];
                a[mt][2] = p0[4]; a[mt][3] = p1[4];
            }
            int bc = wn*64 + lq;
            #pragma unroll
            for (int nt = 0; nt < 8; nt++){
                const float* p = Bs + (size_t)(bc + nt*8)*36 + kb;
                b[nt][0] = p[0]; b[nt][1] = p[4];
            }
            #pragma unroll
            for (int mt = 0; mt < 2; mt++)
                #pragma unroll
                for (int nt = 0; nt < 8; nt++)
                    mma_tf32(acc[mt][nt], a[mt], b[nt]);
        }
    }

    const float cs = 0.31947155f;   // 96^{-1/4}
    float tmax = -1e30f;
    #pragma unroll
    for (int mt = 0; mt < 2; mt++){
        int n = n0 + wm*32 + mt*16 + lq;
        int m = m0 + wn*64 + lr*2;
        float* u0 = U + ((size_t)bh*512 + n)*256;
        float* u1 = U + ((size_t)bh*512 + n + 8)*256;
        #pragma unroll
        for (int nt = 0; nt < 8; nt++){
            float v0 = acc[mt][nt][0]*cs, v1 = acc[mt][nt][1]*cs;
            float v2 = acc[mt][nt][2]*cs, v3 = acc[mt][nt][3]*cs;
            float2 p0; p0.x = v0; p0.y = v1;
            float2 p1; p1.x = v2; p1.y = v3;
            *(float2*)(u0 + m + nt*8) = p0;
            *(float2*)(u1 + m + nt*8) = p1;
            tmax = fmaxf(tmax, fmaxf(fmaxf(v0, v1), fmaxf(v2, v3)));
        }
    }

    // fused diag: rows of X are resident in smem (all 3 K-chunks)
    if (blockIdx.x == 0 && tid < 128){
        float s = 0.f;
        #pragma unroll
        for (int c = 0; c < 3; c++){
            const float* As = sm + c*(2*128*36) + tid*36;
            #pragma unroll
            for (int k = 0; k < 32; k++) s += As[k]*As[k];
        }
        diag[isk*32768 + bh*512 + n0 + tid] = 0.05103103631f * s;  // 0.5/sqrt(96)
    }

    if (isk){
        tmax = wmax(tmax);
        if (lane == 0) red[wid] = tmax;
        __syncthreads();
        if (tid == 0){
            float m = red[0];
            #pragma unroll
            for (int i = 1; i < 8; i++) m = fmaxf(m, red[i]);
            atomicMax(&g_kmax, enc_f(m));
        }
    }
}

// ---------------- ctxT[bh][96e][256m] = sum_n V[n][e]*pk[n][m] ----------------
#define CTX_SV 104
#define CTX_SP 136
#define CTX_STAGEF (32*CTX_SV + 32*CTX_SP)
#define CTX_SMEM (3*CTX_STAGEF*4)
__global__ void __launch_bounds__(256, 2) ctx_mma(
    const float* __restrict__ pk, const float* __restrict__ qkv,
    float* __restrict__ ctxT)
{
    extern __shared__ float sm[];
    int tid = threadIdx.x, lane = tid & 31, wid = tid >> 5;
    int wm = wid & 1, wn = wid >> 1;         // M(e) split 2 (48), N(m) split 4 (32)
    int m0 = blockIdx.x*128, bh = blockIdx.y;
    int b = bh >> 3, h = bh & 7;
    const float* Vb = qkv + (size_t)(b*512)*2304 + 1536 + h*96;
    const float* Pb = pk + (size_t)(bh*512)*256 + m0;
    int lq = lane >> 2, lr = lane & 3;
    uint32_t sb = smem_u32(sm);

    auto ldstage = [&](int s, int c){
        uint32_t ab = sb + (uint32_t)s*CTX_STAGEF*4;
        #pragma unroll
        for (int i = 0; i < 3; i++){
            int p = tid + i*256; int r = p/24, cc = p - r*24;
            CPA16(ab + (uint32_t)(r*CTX_SV + cc*4)*4, Vb + (size_t)(c*32 + r)*2304 + cc*4);
        }
        #pragma unroll
        for (int i = 0; i < 4; i++){
            int p = tid + i*256; int r = p >> 5, cc = p & 31;
            CPA16(ab + (uint32_t)(32*CTX_SV + r*CTX_SP + cc*4)*4,
                  Pb + (size_t)(c*32 + r)*256 + cc*4);
        }
        asm volatile("cp.async.commit_group;");
    };

    float acc[3][4][4];
    #pragma unroll
    for (int mt = 0; mt < 3; mt++)
        #pragma unroll
        for (int nt = 0; nt < 4; nt++)
            #pragma unroll
            for (int r = 0; r < 4; r++) acc[mt][nt][r] = 0.f;

    ldstage(0, 0); ldstage(1, 1); ldstage(2, 2);

    for (int c = 0; c < 16; c++){
        int pend = 15 - c;
        if (pend >= 2)      asm volatile("cp.async.wait_group 2;" ::: "memory");
        else if (pend == 1) asm volatile("cp.async.wait_group 1;" ::: "memory");
        else                asm volatile("cp.async.wait_group 0;" ::: "memory");
        __syncthreads();
        const float* Vs = sm + (c % 3)*CTX_STAGEF;
        const float* Ps = Vs + 32*CTX_SV;

        #pragma unroll
        for (int k8 = 0; k8 < 4; k8++){
            int kb = k8*8 + lr;
            float a[3][4], bfr[4][2];
            int er = wm*48 + lq;
            #pragma unroll
            for (int mt = 0; mt < 3; mt++){
                a[mt][0] = Vs[(size_t)kb*CTX_SV + er + mt*16];
                a[mt][1] = Vs[(size_t)kb*CTX_SV + er + mt*16 + 8];
                a[mt][2] = Vs[(size_t)(kb+4)*CTX_SV + er + mt*16];
                a[mt][3] = Vs[(size_t)(kb+4)*CTX_SV + er + mt*16 + 8];
            }
            int mc = wn*32 + lq;
            #pragma unroll
            for (int nt = 0; nt < 4; nt++){
                bfr[nt][0] = Ps[(size_t)kb*CTX_SP + mc + nt*8];
                bfr[nt][1] = Ps[(size_t)(kb+4)*CTX_SP + mc + nt*8];
            }
            #pragma unroll
            for (int mt = 0; mt < 3; mt++)
                #pragma unroll
                for (int nt = 0; nt < 4; nt++)
                    mma_tf32(acc[mt][nt], a[mt], bfr[nt]);
        }
        __syncthreads();
        if (c + 3 < 16) ldstage(c % 3, c + 3);
    }

    #pragma unroll
    for (int mt = 0; mt < 3; mt++){
        int e = wm*48 + mt*16 + lq;
        int m = m0 + wn*32 + lr*2;
        float* c0 = ctxT + ((size_t)bh*96 + e)*256;
        float* c1 = ctxT + ((size_t)bh*96 + e + 8)*256;
        #pragma unroll
        for (int nt = 0; nt < 4; nt++){
            float2 p0; p0.x = rtf32(acc[mt][nt][0]); p0.y = rtf32(acc[mt][nt][1]);
            float2 p1; p1.x = rtf32(acc[mt][nt][2]); p1.y = rtf32(acc[mt][nt][3]);
            *(float2*)(c0 + m + nt*8) = p0;
            *(float2*)(c1 + m + nt*8) = p1;
        }
    }
}

// ---------------- attn[n][h*96+e] = (pq @ ctxT^T)/den ----------------
#define ATT_STAGEF (128*36 + 96*36)
#define ATT_SMEM (3*ATT_STAGEF*4)
__global__ void __launch_bounds__(256, 2) attn_out_mma(
    const float* __restrict__ pq, const float* __restrict__ ctxT,
    const float* __restrict__ den, float* __restrict__ attn)
{
    extern __shared__ float sm[];
    int tid = threadIdx.x, lane = tid & 31, wid = tid >> 5;
    int wm = wid & 3, wn = wid >> 2;         // M(n) split 4 (32), N(e) split 2 (48)
    int n0 = blockIdx.x*128, bh = blockIdx.y;
    int b = bh >> 3, h = bh & 7;
    const float* Ab = pq + ((size_t)bh*512 + n0)*256;
    const float* Bb = ctxT + (size_t)bh*96*256;
    int lq = lane >> 2, lr = lane & 3;
    uint32_t sb = smem_u32(sm);

    auto ldstage = [&](int s, int c){
        uint32_t ab = sb + (uint32_t)s*ATT_STAGEF*4;
        #pragma unroll
        for (int i = 0; i < 4; i++){
            int p = tid + i*256; int r = p >> 3, c4 = p & 7;
            CPA16(ab + (uint32_t)(r*36 + c4*4)*4, Ab + (size_t)r*256 + c*32 + c4*4);
        }
        #pragma unroll
        for (int i = 0; i < 3; i++){
            int p = tid + i*256; int r = p >> 3, c4 = p & 7;
            CPA16(ab + (uint32_t)(128*36 + r*36 + c4*4)*4, Bb + (size_t)r*256 + c*32 + c4*4);
        }
        asm volatile("cp.async.commit_group;");
    };

    float acc[2][6][4];
    #pragma unroll
    for (int mt = 0; mt < 2; mt++)
        #pragma unroll
        for (int nt = 0; nt < 6; nt++)
            #pragma unroll
            for (int r = 0; r < 4; r++) acc[mt][nt][r] = 0.f;

    ldstage(0, 0); ldstage(1, 1); ldstage(2, 2);

    for (int c = 0; c < 8; c++){
        int pend = 7 - c;
        if (pend >= 2)      asm volatile("cp.async.wait_group 2;" ::: "memory");
        else if (pend == 1) asm volatile("cp.async.wait_group 1;" ::: "memory");
        else                asm volatile("cp.async.wait_group 0;" ::: "memory");
        __syncthreads();
        const float* As = sm + (c % 3)*ATT_STAGEF;
        const float* Bs = As + 128*36;

        #pragma unroll
        for (int k8 = 0; k8 < 4; k8++){
            int kb = k8*8 + lr;
            float a[2][4], bfr[6][2];
            int ar = wm*32 + lq;
            #pragma unroll
            for (int mt = 0; mt < 2; mt++){
                const float* p0 = As + (size_t)(ar + mt*16)*36 + kb;
                const float* p1 = As + (size_t)(ar + mt*16 + 8)*36 + kb;
                a[mt][0] = p0[0]; a[mt][1] = p1[0];
                a[mt][2] = p0[4]; a[mt][3] = p1[4];
            }
            int ec = wn*48 + lq;
            #pragma unroll
            for (int nt = 0; nt < 6; nt++){
                const float* p = Bs + (size_t)(ec + nt*8)*36 + kb;
                bfr[nt][0] = p[0]; bfr[nt][1] = p[4];
            }
            #pragma unroll
            for (int mt = 0; mt < 2; mt++)
                #pragma unroll
                for (int nt = 0; nt < 6; nt++)
                    mma_tf32(acc[mt][nt], a[mt], bfr[nt]);
        }
        __syncthreads();
        if (c + 3 < 8) ldstage(c % 3, c + 3);
    }

    #pragma unroll
    for (int mt = 0; mt < 2; mt++){
        int n = n0 + wm*32 + mt*16 + lq;
        float d0 = 1.f/den[bh*512 + n];
        float d1 = 1.f/den[bh*512 + n + 8];
        float* o0 = attn + (size_t)(b*512 + n)*768 + h*96;
        float* o1 = attn + (size_t)(b*512 + n + 8)*768 + h*96;
        int e = wn*48 + lr*2;
        #pragma unroll
        for (int nt = 0; nt < 6; nt++){
            float2 p0; p0.x = rtf32(acc[mt][nt][0]*d0); p0.y = rtf32(acc[mt][nt][1]*d0);
            float2 p1; p1.x = rtf32(acc[mt][nt][2]*d1); p1.y = rtf32(acc[mt][nt][3]*d1);
            *(float2*)(o0 + e + nt*8) = p0;
            *(float2*)(o1 + e + nt*8) = p1;
        }
    }
}

// ---------------- prep kernels ----------------
__global__ void transpose_w(const float* __restrict__ src, float* __restrict__ dst,
                            int K, int N)
{
    __shared__ float t[32][33];
    int n0 = blockIdx.x*32, k0 = blockIdx.y*32;
    size_t off = (size_t)blockIdx.z * (size_t)K * N;
    src += off; dst += off;
    int tx = threadIdx.x & 31, ty = threadIdx.x >> 5;
    #pragma unroll
    for (int i = 0; i < 32; i += 8)
        t[ty+i][tx] = src[(size_t)(k0+ty+i)*N + n0+tx];
    __syncthreads();
    #pragma unroll
    for (int i = 0; i < 32; i += 8)
        dst[(size_t)(n0+ty+i)*K + k0+tx] = rtf32(t[tx][ty+i]);
}

__global__ void copy_round(const float* __restrict__ src, float* __restrict__ dst){
    int i = blockIdx.x*256 + threadIdx.x;
    dst[i] = rtf32(src[i]);
}

__global__ void im2col_kernel(const float* __restrict__ mel, float* __restrict__ dst){
    int idx = blockIdx.x*256 + threadIdx.x;
    int pg = idx >> 8, k = idx & 255;
    int b = pg >> 9, p = pg & 511;
    int oh = p >> 3, ow = p & 7;
    int i = k >> 4, j = k & 15;
    dst[idx] = rtf32(mel[(size_t)b*131072 + (size_t)(oh*16 + i)*128 + ow*16 + j]);
}

// ---------------- layernorm (also resets g_kmax for the upcoming phi) ----------------
__global__ void ln_kernel(const float* __restrict__ X, const float* __restrict__ sc,
                          const float* __restrict__ bb, float* __restrict__ Y)
{
    __shared__ float s1[8], s2[8];
    int row = blockIdx.x, tid = threadIdx.x;
    if (row == 0 && tid == 0) g_kmax = 0u;
    int lane = tid & 31, wid = tid >> 5;
    const float* xr = X + (size_t)row*DMODEL;
    float v[3]; float sum = 0.f, sq = 0.f;
    #pragma unroll
    for (int i = 0; i < 3; i++){
        v[i] = xr[tid + 256*i];
        sum += v[i]; sq += v[i]*v[i];
    }
    sum = wsum(sum); sq = wsum(sq);
    if (lane == 0){ s1[wid] = sum; s2[wid] = sq; }
    __syncthreads();
    if (tid == 0){
        float a = 0.f, b2 = 0.f;
        #pragma unroll
        for (int i = 0; i < 8; i++){ a += s1[i]; b2 += s2[i]; }
        s1[0] = a; s2[0] = b2;
    }
    __syncthreads();
    float mean = s1[0]*(1.f/768.f);
    float var  = s2[0]*(1.f/768.f) - mean*mean;
    float rstd = rsqrtf(var + 1e-5f);
    float* yr = Y + (size_t)row*DMODEL;
    #pragma unroll
    for (int i = 0; i < 3; i++){
        int d = tid + 256*i;
        yr[d] = rtf32((v[i] - mean)*rstd*sc[d] + bb[d]);
    }
}

// ---------------- FAVOR+ finalize ----------------
__global__ void pk_fin_part(float* __restrict__ U, const float* __restrict__ diagk,
                            float* __restrict__ pspart)
{
    int bh = blockIdx.x, ch = blockIdx.y, m = threadIdx.x;
    float kst = dec_f(g_kmax);
    float* u = U + ((size_t)bh*512 + ch*64)*256 + m;
    const float* dg = diagk + bh*512 + ch*64;
    float s = 0.f;
    #pragma unroll 4
    for (int n = 0; n < 64; n++){
        float v = u[(size_t)n*256];
        float e = rtf32((expf(v - dg[n] - kst) + 1e-4f)*0.0625f);
        u[(size_t)n*256] = e;
        s += e;
    }
    pspart[((size_t)bh*8 + ch)*256 + m] = s;
}

__global__ void ps_reduce(const float* __restrict__ pspart, float* __restrict__ ps)
{
    int bh = blockIdx.x, m = threadIdx.x;
    const float* p = pspart + (size_t)bh*8*256 + m;
    float s = 0.f;
    #pragma unroll
    for (int c = 0; c < 8; c++) s += p[c*256];
    ps[bh*256 + m] = s;
}

__global__ void pq_fin_den(float* __restrict__ U, const float* __restrict__ diagq,
                           const float* __restrict__ ps, float* __restrict__ den)
{
    int gw = blockIdx.x*8 + (threadIdx.x >> 5);
    int lane = threadIdx.x & 31;
    int bh = gw >> 9;
    float* u = U + (size_t)gw*256;
    const float* s = ps + bh*256;
    float v[8]; float m = -1e30f;
    #pragma unroll
    for (int i = 0; i < 8; i++){ v[i] = u[lane + 32*i]; m = fmaxf(m, v[i]); }
    m = wmax(m);
    float d = diagq[gw];
    float a = 0.f;
    #pragma unroll
    for (int i = 0; i < 8; i++){
        float e = rtf32((expf(v[i] - d - m) + 1e-4f)*0.0625f);
        u[lane + 32*i] = e;
        a += e*s[lane + 32*i];
    }
    a = wsum(a);
    if (lane == 0) den[gw] = a;
}

// ---------------- mask head ----------------
__global__ void mask_kernel(const float* __restrict__ X, const float* __restrict__ mw,
                            const float* __restrict__ mb, float* __restrict__ out)
{
    int row = blockIdx.x;
    int tid = threadIdx.x;
    int w = tid >> 5, lane = tid & 31;
    const float* xr = X + (size_t)row*768;
    float s = 0.f;
    for (int d = lane; d < 768; d += 32) s += xr[d]*mw[d*4 + w];
    s = wsum(s);
    if (lane == 0){
        float logit = s + mb[w];
        int b = row >> 9, n = row & 511;
        out[((size_t)b*4 + w)*512 + n] = 1.f/(1.f + expf(-logit));
    }
}

// ---------------- driver ----------------
extern "C" void kernel_launch(void* const* d_in, const int* in_sizes, int n_in,
                              void* d_out, int out_size)
{
    (void)in_sizes; (void)n_in; (void)out_size;
    const float* mel     = (const float*)d_in[0];
    const float* patch_w = (const float*)d_in[1];
    const float* patch_b = (const float*)d_in[2];
    const float* pos     = (const float*)d_in[3];
    const float* proj    = (const float*)d_in[4];
    const float* ln1_s   = (const float*)d_in[5];
    const float* ln1_b   = (const float*)d_in[6];
    const float* qkv_w   = (const float*)d_in[7];
    const float* qkv_b   = (const float*)d_in[8];
    const float* ao_w    = (const float*)d_in[9];
    const float* ao_b    = (const float*)d_in[10];
    const float* ln2_s   = (const float*)d_in[11];
    const float* ln2_b   = (const float*)d_in[12];
    const float* ff1_w   = (const float*)d_in[13];
    const float* ff1_b   = (const float*)d_in[14];
    const float* ff2_w   = (const float*)d_in[15];
    const float* ff2_b   = (const float*)d_in[16];
    const float* mask_w  = (const float*)d_in[17];
    const float* mask_b  = (const float*)d_in[18];
    float* out = (float*)d_out;

    float *x, *lnb, *qkv, *ffb, *uq, *uk, *ctxb, *attn, *diag, *ps, *psp, *den, *im2, *pwT;
    float *wtq, *wtao, *wtf1, *wtf2;
    cudaGetSymbolAddress((void**)&x,    g_x);
    cudaGetSymbolAddress((void**)&lnb,  g_lnbuf);
    cudaGetSymbolAddress((void**)&qkv,  g_qkv);
    cudaGetSymbolAddress((void**)&ffb,  g_ffbuf);
    cudaGetSymbolAddress((void**)&uq,   g_uq);
    cudaGetSymbolAddress((void**)&uk,   g_uk);
    cudaGetSymbolAddress((void**)&ctxb, g_ctxb);
    cudaGetSymbolAddress((void**)&attn, g_attn);
    cudaGetSymbolAddress((void**)&diag, g_diag);
    cudaGetSymbolAddress((void**)&ps,   g_pksum);
    cudaGetSymbolAddress((void**)&psp,  g_pspart);
    cudaGetSymbolAddress((void**)&den,  g_den);
    cudaGetSymbolAddress((void**)&im2,  g_im2col);
    cudaGetSymbolAddress((void**)&pwT,  g_pwT);
    cudaGetSymbolAddress((void**)&wtq,  g_wt_qkv);
    cudaGetSymbolAddress((void**)&wtao, g_wt_ao);
    cudaGetSymbolAddress((void**)&wtf1, g_wt_ff1);
    cudaGetSymbolAddress((void**)&wtf2, g_wt_ff2);

    cudaFuncSetAttribute(gemm_tc, cudaFuncAttributeMaxDynamicSharedMemorySize, GEMM_SMEM);
    cudaFuncSetAttribute(phi_u_mma, cudaFuncAttributeMaxDynamicSharedMemorySize, PHI_SMEM);
    cudaFuncSetAttribute(ctx_mma, cudaFuncAttributeMaxDynamicSharedMemorySize, CTX_SMEM);
    cudaFuncSetAttribute(attn_out_mma, cudaFuncAttributeMaxDynamicSharedMemorySize, ATT_SMEM);

    // weight prep
    copy_round<<<768, 256>>>(patch_w, pwT);
    transpose_w<<<dim3(72, 24, 6), 256>>>(qkv_w, wtq, 768, 2304);
    transpose_w<<<dim3(24, 24, 6), 256>>>(ao_w,  wtao, 768, 768);
    transpose_w<<<dim3(96, 24, 6), 256>>>(ff1_w, wtf1, 768, 3072);
    transpose_w<<<dim3(24, 96, 6), 256>>>(ff2_w, wtf2, 3072, 768);

    // patch embed
    im2col_kernel<<<4096, 256>>>(mel, im2);
    gemm_tc<<<dim3(6, 32), 128, GEMM_SMEM>>>(im2, pwT, patch_b, x, 256, 768, 3, pos);

    for (int l = 0; l < NDEPTH; l++){
        ln_kernel<<<4096, 256>>>(x, ln1_s + l*768, ln1_b + l*768, lnb);
        gemm_tc<<<dim3(18, 32), 128, GEMM_SMEM>>>(
            lnb, wtq + (size_t)l*2304*768, qkv_b + l*2304, qkv, 768, 2304, 0, 0);
        phi_u_mma<<<dim3(2, 4, 128), 256, PHI_SMEM>>>(qkv, proj, uq, uk, diag);
        pk_fin_part<<<dim3(64, 8), 256>>>(uk, diag + 32768, psp);
        ps_reduce<<<64, 256>>>(psp, ps);
        pq_fin_den<<<4096, 256>>>(uq, diag, ps, den);
        ctx_mma<<<dim3(2, 64), 256, CTX_SMEM>>>(uk, qkv, ctxb);
        attn_out_mma<<<dim3(4, 64), 256, ATT_SMEM>>>(uq, ctxb, den, attn);
        gemm_tc<<<dim3(6, 32), 128, GEMM_SMEM>>>(
            attn, wtao + (size_t)l*768*768, ao_b + l*768, x, 768, 768, 2, 0);
        ln_kernel<<<4096, 256>>>(x, ln2_s + l*768, ln2_b + l*768, lnb);
        gemm_tc<<<dim3(24, 32), 128, GEMM_SMEM>>>(
            lnb, wtf1 + (size_t)l*768*3072, ff1_b + l*3072, ffb, 768, 3072, 1, 0);
        gemm_tc<<<dim3(6, 32), 128, GEMM_SMEM>>>(
            ffb, wtf2 + (size_t)l*3072*768, ff2_b + l*768, x, 3072, 768, 2, 0);
    }

    mask_kernel<<<4096, 128>>>(x, mask_w, mask_b, out);
}